// round 12
// baseline (speedup 1.0000x reference)
#include <cuda_runtime.h>
#include <cuda_bf16.h>
#include <cstdint>

#define N_NODES 8192
#define D 128
#define KNBR 8
#define LN_EPS 1e-5f

#define M_PLAIN 0
#define M_RELU  1
#define M_LN    2

#define MTILE 64
#define THREADS 256
// SMEM (bytes): Ah[64x128 bf16]=16K @0, Al @16384, W plane @32768 (32K)
#define OFF_AL 16384
#define OFF_W  32768
#define SMEM_TOTAL 65536
#define WPLANE 32768           // one W plane [128 n][128 k] bf16
#define ROWB 256               // bytes per activation row per plane (128 bf16)

// ---------------- device globals (no allocation allowed) -------------------
// activation planes: hi/lo bf16, swizzled rows (chunk ch at ((ch^(r&7))<<4))
__device__ __align__(16) unsigned char g_xh[N_NODES * ROWB];
__device__ __align__(16) unsigned char g_xl[N_NODES * ROWB];
__device__ __align__(16) unsigned char g_h0[N_NODES * ROWB];
__device__ __align__(16) unsigned char g_l0[N_NODES * ROWB];
__device__ __align__(16) unsigned char g_h1[N_NODES * ROWB];
__device__ __align__(16) unsigned char g_l1[N_NODES * ROWB];
__device__ __align__(16) unsigned char g_h2[N_NODES * ROWB];
__device__ __align__(16) unsigned char g_l2[N_NODES * ROWB];
__device__ __align__(16) unsigned char g_h3[N_NODES * ROWB];
__device__ __align__(16) unsigned char g_l3[N_NODES * ROWB];
__device__ float g_dinv[N_NODES];
__device__ int   g_kcnt[N_NODES];
__device__ __align__(16) int g_gn[N_NODES * KNBR];      // gcn kept list, pad=i
__device__ __align__(16) int g_pooln[N_NODES * KNBR];   // pool list, pad=first
__device__ float g_pmul[N_NODES];                       // 0 if leaf else 1
// pre-split, pre-swizzled weights: 10 chunks, hi/lo planes of 32KB
__device__ __align__(16) unsigned char g_wh[10 * WPLANE];
__device__ __align__(16) unsigned char g_wl[10 * WPLANE];

// ---------------- job descriptors -------------------------------------------
struct GJob {
    const unsigned char *ah, *al;     // A chunk-0 planes
    const unsigned char *ph, *pl;     // pool source planes (chunk 1)
    const unsigned char *rh, *rl;     // residual planes (LN)
    const float *bias, *lng, *lnb;
    float* outf;                      // fp32 out (or null)
    unsigned char *oh, *ol;           // hi/lo out (if outf null)
    int wchunk, nchunks, mode, ostride, ooff;
};
struct PJob {
    const unsigned char *nh, *nl;     // nxt planes
    const unsigned char *rh, *rl;     // res planes
    const float *lng, *lnb;
    float* outf;
    unsigned char *oh, *ol;
    int ostride, ooff;
};

// ---------------- helpers ---------------------------------------------------
__device__ __forceinline__ uint32_t smem_u32(const void* p) {
    uint32_t a;
    asm("{ .reg .u64 t; cvta.to.shared.u64 t, %1; cvt.u32.u64 %0, t; }"
        : "=r"(a) : "l"(p));
    return a;
}
__device__ __forceinline__ void ldsm4(uint32_t addr, uint32_t* r) {
    asm volatile("ldmatrix.sync.aligned.m8n8.x4.shared.b16 {%0,%1,%2,%3}, [%4];"
                 : "=r"(r[0]), "=r"(r[1]), "=r"(r[2]), "=r"(r[3]) : "r"(addr));
}
__device__ __forceinline__ void mma_bf16(float* d, const uint32_t* a,
                                         uint32_t b0, uint32_t b1) {
    asm volatile(
        "mma.sync.aligned.m16n8k16.row.col.f32.bf16.bf16.f32 "
        "{%0,%1,%2,%3}, {%4,%5,%6,%7}, {%8,%9}, {%0,%1,%2,%3};"
        : "+f"(d[0]), "+f"(d[1]), "+f"(d[2]), "+f"(d[3])
        : "r"(a[0]), "r"(a[1]), "r"(a[2]), "r"(a[3]), "r"(b0), "r"(b1));
}
__device__ __forceinline__ void bulk_g2s(uint32_t dst, const void* src,
                                         uint32_t bytes, uint32_t mbar) {
    asm volatile(
        "cp.async.bulk.shared::cluster.global.mbarrier::complete_tx::bytes "
        "[%0], [%1], %2, [%3];"
        :: "r"(dst), "l"(src), "r"(bytes), "r"(mbar) : "memory");
}
__device__ __forceinline__ void mbar_init(uint32_t a, uint32_t cnt) {
    asm volatile("mbarrier.init.shared.b64 [%0], %1;" :: "r"(a), "r"(cnt) : "memory");
}
__device__ __forceinline__ void mbar_expect_tx(uint32_t a, uint32_t tx) {
    asm volatile("mbarrier.arrive.expect_tx.shared.b64 _, [%0], %1;"
                 :: "r"(a), "r"(tx) : "memory");
}
__device__ __forceinline__ void mbar_wait(uint32_t a, uint32_t parity) {
    asm volatile(
        "{\n\t.reg .pred P;\n\t"
        "WL_%=:\n\t"
        "mbarrier.try_wait.parity.acquire.cta.shared::cta.b64 P, [%0], %1, 0x989680;\n\t"
        "@P bra.uni WD_%=;\n\t"
        "bra.uni WL_%=;\n\t"
        "WD_%=:\n\t}"
        :: "r"(a), "r"(parity) : "memory");
}
static __device__ __forceinline__ uint32_t bf2u(__nv_bfloat162 v) {
    return *reinterpret_cast<uint32_t*>(&v);
}
// pack 8 floats -> hi uint4 / lo uint4 (bf16 pairs)
__device__ __forceinline__ void split8(const float* f, uint4& hi, uint4& lo) {
    __nv_bfloat16 h[8];
    float l[8];
#pragma unroll
    for (int e = 0; e < 8; ++e) {
        h[e] = __float2bfloat16(f[e]);
        l[e] = f[e] - __bfloat162float(h[e]);
    }
    hi.x = bf2u(__halves2bfloat162(h[0], h[1]));
    hi.y = bf2u(__halves2bfloat162(h[2], h[3]));
    hi.z = bf2u(__halves2bfloat162(h[4], h[5]));
    hi.w = bf2u(__halves2bfloat162(h[6], h[7]));
    lo.x = bf2u(__floats2bfloat162_rn(l[0], l[1]));
    lo.y = bf2u(__floats2bfloat162_rn(l[2], l[3]));
    lo.z = bf2u(__floats2bfloat162_rn(l[4], l[5]));
    lo.w = bf2u(__floats2bfloat162_rn(l[6], l[7]));
}
// reconstruct 8 fp32 from one swizzled 16B hi + 16B lo chunk
__device__ __forceinline__ void rec8(const unsigned char* hp,
                                     const unsigned char* lp,
                                     uint32_t off, float* v) {
    uint4 h = *(const uint4*)(hp + off);
    uint4 l = *(const uint4*)(lp + off);
    float2 p, q;
    p = __bfloat1622float2(*(const __nv_bfloat162*)&h.x);
    q = __bfloat1622float2(*(const __nv_bfloat162*)&l.x);
    v[0] = p.x + q.x; v[1] = p.y + q.y;
    p = __bfloat1622float2(*(const __nv_bfloat162*)&h.y);
    q = __bfloat1622float2(*(const __nv_bfloat162*)&l.y);
    v[2] = p.x + q.x; v[3] = p.y + q.y;
    p = __bfloat1622float2(*(const __nv_bfloat162*)&h.z);
    q = __bfloat1622float2(*(const __nv_bfloat162*)&l.z);
    v[4] = p.x + q.x; v[5] = p.y + q.y;
    p = __bfloat1622float2(*(const __nv_bfloat162*)&h.w);
    q = __bfloat1622float2(*(const __nv_bfloat162*)&l.w);
    v[6] = p.x + q.x; v[7] = p.y + q.y;
}
__device__ __forceinline__ uint32_t swz(int r, int ch) {
    return (uint32_t)r * ROWB + ((uint32_t)(ch ^ (r & 7)) << 4);
}

// ---------------- prep: W split (0-9), graph (10-41), x convert (42-169) ---
__global__ void prep_all_kernel(const int* __restrict__ neigh,
                                const int* __restrict__ nbrc,
                                const float* __restrict__ gW,
                                const float* __restrict__ pW,
                                const float* __restrict__ mW,
                                const float* __restrict__ x) {
    int c = blockIdx.x, tid = threadIdx.x;
    if (c >= 42) {                       // x -> hi/lo swizzled planes
        int base = (c - 42) * 64;
#pragma unroll
        for (int it = 0; it < 4; ++it) {
            int idx = tid + it * 256;
            int r = base + (idx >> 4), ch = idx & 15;
            float f[8];
            float4 f0 = *(const float4*)&x[r * D + ch * 8];
            float4 f1 = *(const float4*)&x[r * D + ch * 8 + 4];
            f[0]=f0.x; f[1]=f0.y; f[2]=f0.z; f[3]=f0.w;
            f[4]=f1.x; f[5]=f1.y; f[6]=f1.z; f[7]=f1.w;
            uint4 hi, lo;
            split8(f, hi, lo);
            uint32_t off = swz(r, ch);
            *(uint4*)(g_xh + off) = hi;
            *(uint4*)(g_xl + off) = lo;
        }
        return;
    }
    if (c >= 10) {                       // graph tables
        int i = (c - 10) * 256 + tid;
        int cnt = nbrc[i];
        cnt = cnt > KNBR ? KNBR : (cnt < 0 ? 0 : cnt);
        int first = cnt > 0 ? neigh[i * KNBR] : 0;
#pragma unroll
        for (int k = 0; k < KNBR; ++k)
            g_pooln[i * KNBR + k] = k < cnt ? neigh[i * KNBR + k] : first;
        g_pmul[i] = cnt > 0 ? 1.f : 0.f;
        int kept[KNBR];
        int kc = 0;
        for (int k = 0; k < cnt; ++k) {
            int nb = neigh[i * KNBR + k];
            if (nb == i) continue;
            bool dup = false;
            for (int t = 0; t < kc; ++t) if (kept[t] == nb) dup = true;
            if (!dup) kept[kc++] = nb;
        }
#pragma unroll
        for (int k = 0; k < KNBR; ++k)
            g_gn[i * KNBR + k] = k < kc ? kept[k] : i;
        g_kcnt[i] = kc;
        g_dinv[i] = rsqrtf((float)(kc + 1));
        return;
    }
    // W chunks
    const float* src;
    int stride, coloff;
    if (c < 3)       { src = gW + c * 16384; stride = 128; coloff = 0; }
    else if (c == 3) { src = pW;             stride = 128; coloff = 0; }
    else { int l = (c - 4) >> 1, h = (c - 4) & 1;
           src = mW + l * 32768; stride = 256; coloff = h * 128; }
    unsigned char* wh = g_wh + c * WPLANE;
    unsigned char* wl = g_wl + c * WPLANE;
    for (int i = tid; i < 2048; i += 256) {
        int n = i >> 4, ch = i & 15;
        float f[8];
#pragma unroll
        for (int e = 0; e < 8; ++e) f[e] = src[n * stride + coloff + ch * 8 + e];
        uint4 hi, lo;
        split8(f, hi, lo);
        uint32_t off = swz(n, ch);
        *(uint4*)(wh + off) = hi;
        *(uint4*)(wl + off) = lo;
    }
}

// one pass: acc += A(aB) @ W(wB)^T for this warp's 32x32 tile
__device__ __forceinline__ void gemm_pass(uint32_t aB, uint32_t wB,
                                          int rowA0, int rowA1,
                                          int rowB0, int rowB1, int lhalf,
                                          float acc[2][4][4]) {
#pragma unroll
    for (int ks = 0; ks < 8; ++ks) {
        const int ch = ks * 2 + lhalf;
        uint32_t a0[4], a1[4], b0[4], b1[4];
        ldsm4(aB + swz(rowA0, ch), a0);
        ldsm4(aB + swz(rowA1, ch), a1);
        ldsm4(wB + swz(rowB0, ch), b0);
        ldsm4(wB + swz(rowB1, ch), b1);
        mma_bf16(acc[0][0], a0, b0[0], b0[2]);
        mma_bf16(acc[0][1], a0, b0[1], b0[3]);
        mma_bf16(acc[0][2], a0, b1[0], b1[2]);
        mma_bf16(acc[0][3], a0, b1[1], b1[3]);
        mma_bf16(acc[1][0], a1, b0[0], b0[2]);
        mma_bf16(acc[1][1], a1, b0[1], b0[3]);
        mma_bf16(acc[1][2], a1, b1[0], b1[2]);
        mma_bf16(acc[1][3], a1, b1[1], b1[3]);
    }
}

// ---------------- GEMM body: out = [A | pool(psrc)] @ W^T + b --------------
// hi/lo: D = Ah@Wh + Al@Wh + Ah@Wl, W streamed one 32KB plane at a time.
__device__ void gemm_body(const GJob& J, int bid, char* smem_raw) {
    __shared__ __align__(8) uint64_t s_mbar;
    const uint32_t sbase = smem_u32(smem_raw);
    const uint32_t mbar = smem_u32(&s_mbar);
    const int tid = threadIdx.x, wid = tid >> 5, lane = tid & 31;
    const int wm = wid & 1, wn = wid >> 1;
    const int m0 = bid * MTILE;

    if (tid == 0) mbar_init(mbar, 1);
    __syncthreads();

    float acc[2][4][4];
#pragma unroll
    for (int i = 0; i < 2; ++i)
#pragma unroll
        for (int j = 0; j < 4; ++j)
#pragma unroll
            for (int r = 0; r < 4; ++r) acc[i][j][r] = 0.f;

    const int lrow = lane & 15, lhalf = lane >> 4;
    const int rowA0 = wm * 32 + lrow, rowA1 = rowA0 + 16;
    const int rowB0 = wn * 32 + lrow, rowB1 = rowB0 + 16;

    int ph = 0;
    for (int c = 0; c < J.nchunks; ++c) {
        if (c) __syncthreads();             // prior chunk done with A and W
        if (tid == 0) {
            mbar_expect_tx(mbar, 32768u + (c == 0 ? 32768u : 0u));
            bulk_g2s(sbase + OFF_W, g_wh + (J.wchunk + c) * WPLANE, WPLANE, mbar);
            if (c == 0) {
                bulk_g2s(sbase,          J.ah + (size_t)m0 * ROWB, 16384, mbar);
                bulk_g2s(sbase + OFF_AL, J.al + (size_t)m0 * ROWB, 16384, mbar);
            }
        }
        if (c == 1) {
            // fused max-pool gather into A smem planes (hi/lo, swizzled)
            for (int i = tid; i < 1024; i += THREADS) {
                int r = i >> 4, ch = i & 15;
                int node = m0 + r;
                const int4* nl = (const int4*)(g_pooln + node * KNBR);
                int4 na = nl[0], nb = nl[1];
                float pm = g_pmul[node];
                int idx[8] = { na.x, na.y, na.z, na.w, nb.x, nb.y, nb.z, nb.w };
                float mv[8], tv[8];
                rec8(J.ph, J.pl, swz(idx[0], ch), mv);
#pragma unroll
                for (int t = 1; t < 8; ++t) {
                    rec8(J.ph, J.pl, swz(idx[t], ch), tv);
#pragma unroll
                    for (int e = 0; e < 8; ++e) mv[e] = fmaxf(mv[e], tv[e]);
                }
#pragma unroll
                for (int e = 0; e < 8; ++e) mv[e] *= pm;
                uint4 hi, lo;
                split8(mv, hi, lo);
                uint32_t off = swz(r, ch);
                *(uint4*)(smem_raw + off) = hi;
                *(uint4*)(smem_raw + OFF_AL + off) = lo;
            }
        }
        __syncthreads();                    // gather visible
        mbar_wait(mbar, ph & 1); ph++;      // Wh (+A) arrived
        gemm_pass(sbase,          sbase + OFF_W, rowA0, rowA1, rowB0, rowB1, lhalf, acc);
        gemm_pass(sbase + OFF_AL, sbase + OFF_W, rowA0, rowA1, rowB0, rowB1, lhalf, acc);
        __syncthreads();                    // all warps done reading Wh
        if (tid == 0) {
            mbar_expect_tx(mbar, 32768u);
            bulk_g2s(sbase + OFF_W, g_wl + (J.wchunk + c) * WPLANE, WPLANE, mbar);
        }
        mbar_wait(mbar, ph & 1); ph++;      // Wl arrived
        gemm_pass(sbase,          sbase + OFF_W, rowA0, rowA1, rowB0, rowB1, lhalf, acc);
    }

    // ---- epilogue: fragments -> sC fp32 (bias [+relu]) -> per-row finish --
    const int frow = lane >> 2, fcol = 2 * (lane & 3);
    float* sC = (float*)smem_raw;                 // [64][132]
    __syncthreads();
#pragma unroll
    for (int i = 0; i < 2; ++i)
#pragma unroll
        for (int j = 0; j < 4; ++j) {
            int ncol = wn * 32 + j * 8 + fcol;
            float2 bj = *(const float2*)&J.bias[ncol];
            int r = wm * 32 + i * 16 + frow;
            float v0 = acc[i][j][0] + bj.x, v1 = acc[i][j][1] + bj.y;
            float v2 = acc[i][j][2] + bj.x, v3 = acc[i][j][3] + bj.y;
            if (J.mode != M_PLAIN) {
                v0 = fmaxf(v0, 0.f); v1 = fmaxf(v1, 0.f);
                v2 = fmaxf(v2, 0.f); v3 = fmaxf(v3, 0.f);
            }
            sC[r * 132 + ncol]           = v0;
            sC[r * 132 + ncol + 1]       = v1;
            sC[(r + 8) * 132 + ncol]     = v2;
            sC[(r + 8) * 132 + ncol + 1] = v3;
        }
    __syncthreads();

    {
        const int row = tid >> 2, q = tid & 3;     // 4 threads/row, 64 rows
        const int m = m0 + row;
        float mean = 0.f, rstd = 1.f;
        if (J.mode == M_LN) {
            float s = 0.f, ss = 0.f;
#pragma unroll
            for (int cq = 0; cq < 4; ++cq) {
                float r8[8];
                rec8(J.rh, J.rl, swz(m, q * 4 + cq), r8);
                float* cp = &sC[row * 132 + q * 32 + cq * 8];
                float4 a0 = *(float4*)cp, a1 = *(float4*)(cp + 4);
                a0.x += r8[0]; a0.y += r8[1]; a0.z += r8[2]; a0.w += r8[3];
                a1.x += r8[4]; a1.y += r8[5]; a1.z += r8[6]; a1.w += r8[7];
                s  += a0.x + a0.y + a0.z + a0.w + a1.x + a1.y + a1.z + a1.w;
                ss += a0.x * a0.x + a0.y * a0.y + a0.z * a0.z + a0.w * a0.w +
                      a1.x * a1.x + a1.y * a1.y + a1.z * a1.z + a1.w * a1.w;
                *(float4*)cp = a0;
                *(float4*)(cp + 4) = a1;
            }
#pragma unroll
            for (int off = 1; off < 4; off <<= 1) {
                s  += __shfl_xor_sync(0xffffffffu, s,  off);
                ss += __shfl_xor_sync(0xffffffffu, ss, off);
            }
            mean = s * (1.0f / 128.0f);
            rstd = rsqrtf(ss * (1.0f / 128.0f) - mean * mean + LN_EPS);
        }
#pragma unroll
        for (int cq = 0; cq < 4; ++cq) {
            int col = q * 32 + cq * 8;
            float* cp = &sC[row * 132 + col];
            float v[8];
            *(float4*)&v[0] = *(float4*)cp;
            *(float4*)&v[4] = *(float4*)(cp + 4);
            if (J.mode == M_LN) {
                float4 g0 = *(const float4*)&J.lng[col];
                float4 g1 = *(const float4*)&J.lng[col + 4];
                float4 o0 = *(const float4*)&J.lnb[col];
                float4 o1 = *(const float4*)&J.lnb[col + 4];
                v[0] = (v[0] - mean) * rstd * g0.x + o0.x;
                v[1] = (v[1] - mean) * rstd * g0.y + o0.y;
                v[2] = (v[2] - mean) * rstd * g0.z + o0.z;
                v[3] = (v[3] - mean) * rstd * g0.w + o0.w;
                v[4] = (v[4] - mean) * rstd * g1.x + o1.x;
                v[5] = (v[5] - mean) * rstd * g1.y + o1.y;
                v[6] = (v[6] - mean) * rstd * g1.z + o1.z;
                v[7] = (v[7] - mean) * rstd * g1.w + o1.w;
            }
            if (J.outf) {
                *(float4*)&J.outf[(size_t)m * J.ostride + J.ooff + col]     = *(float4*)&v[0];
                *(float4*)&J.outf[(size_t)m * J.ostride + J.ooff + col + 4] = *(float4*)&v[4];
            } else {
                uint4 hi, lo;
                split8(v, hi, lo);
                uint32_t off = swz(m, q * 4 + cq);
                *(uint4*)(J.oh + off) = hi;
                *(uint4*)(J.ol + off) = lo;
            }
        }
    }
}

// ---------------- prop body: 64 nodes/block, 2 nodes/warp, 16-lane rows ----
__device__ void prop_body(const PJob& P, int blk) {
    const int lane = threadIdx.x & 31, wid = threadIdx.x >> 5;
    const int half = lane >> 4, ch = lane & 15;
    for (int t = 0; t < 4; ++t) {
        const int i = blk * 64 + t * 16 + wid * 2 + half;
        const float di = g_dinv[i];
        float a[8], acc[8];
        rec8(P.nh, P.nl, swz(i, ch), a);
#pragma unroll
        for (int e = 0; e < 8; ++e) acc[e] = di * a[e];
        const int kc = g_kcnt[i];
        const int* kn = g_gn + i * KNBR;
        for (int k = 0; k < kc; ++k) {
            int j = kn[k];
            float dj = g_dinv[j];
            rec8(P.nh, P.nl, swz(j, ch), a);
#pragma unroll
            for (int e = 0; e < 8; ++e) acc[e] += dj * a[e];
        }
        rec8(P.rh, P.rl, swz(i, ch), a);           // residual
        float v[8];
        float s = 0.f, ss = 0.f;
#pragma unroll
        for (int e = 0; e < 8; ++e) {
            v[e] = fmaxf(di * acc[e], 0.f) + a[e];
            s += v[e]; ss += v[e] * v[e];
        }
#pragma unroll
        for (int off = 1; off < 16; off <<= 1) {
            s  += __shfl_xor_sync(0xffffffffu, s,  off);
            ss += __shfl_xor_sync(0xffffffffu, ss, off);
        }
        float mean = s * (1.0f / 128.0f);
        float rstd = rsqrtf(ss * (1.0f / 128.0f) - mean * mean + LN_EPS);
        float4 g0 = *(const float4*)&P.lng[ch * 8];
        float4 g1 = *(const float4*)&P.lng[ch * 8 + 4];
        float4 o0 = *(const float4*)&P.lnb[ch * 8];
        float4 o1 = *(const float4*)&P.lnb[ch * 8 + 4];
        v[0] = (v[0] - mean) * rstd * g0.x + o0.x;
        v[1] = (v[1] - mean) * rstd * g0.y + o0.y;
        v[2] = (v[2] - mean) * rstd * g0.z + o0.z;
        v[3] = (v[3] - mean) * rstd * g0.w + o0.w;
        v[4] = (v[4] - mean) * rstd * g1.x + o1.x;
        v[5] = (v[5] - mean) * rstd * g1.y + o1.y;
        v[6] = (v[6] - mean) * rstd * g1.z + o1.z;
        v[7] = (v[7] - mean) * rstd * g1.w + o1.w;
        if (P.outf) {
            *(float4*)&P.outf[(size_t)i * P.ostride + P.ooff + ch * 8]     = *(float4*)&v[0];
            *(float4*)&P.outf[(size_t)i * P.ostride + P.ooff + ch * 8 + 4] = *(float4*)&v[4];
        } else {
            uint4 hi, lo;
            split8(v, hi, lo);
            uint32_t off = swz(i, ch);
            *(uint4*)(P.oh + off) = hi;
            *(uint4*)(P.ol + off) = lo;
        }
    }
}

#define GB (N_NODES / MTILE)    // 128 gemm tiles
#define PB (N_NODES / 64)       // 128 prop blocks

// ---------------- named step kernels ----------------------------------------
__global__ __launch_bounds__(THREADS, 3) void k_g2(GJob g0, GJob g1) {
    extern __shared__ __align__(256) char smem_raw[];
    int b = blockIdx.x;
    if (b < GB) gemm_body(g0, b, smem_raw);
    else        gemm_body(g1, b - GB, smem_raw);
}
__global__ __launch_bounds__(THREADS, 3) void k_gp(GJob g, PJob p) {
    extern __shared__ __align__(256) char smem_raw[];
    int b = blockIdx.x;
    if (b < GB) gemm_body(g, b, smem_raw);
    else        prop_body(p, b - GB);
}
__global__ __launch_bounds__(THREADS, 3) void k_g1(GJob g) {
    extern __shared__ __align__(256) char smem_raw[];
    gemm_body(g, blockIdx.x, smem_raw);
}
__global__ __launch_bounds__(THREADS) void k_p(PJob p) {
    prop_body(p, blockIdx.x);
}

// ---------------- driver ----------------------------------------------------
extern "C" void kernel_launch(void* const* d_in, const int* in_sizes, int n_in,
                              void* d_out, int out_size) {
    const float* x   = (const float*)d_in[0];
    const int*   nei = (const int*)  d_in[1];
    const int*   nbc = (const int*)  d_in[2];
    const float* gW  = (const float*)d_in[3];
    const float* gb  = (const float*)d_in[4];
    const float* glg = (const float*)d_in[5];
    const float* glb = (const float*)d_in[6];
    const float* pW  = (const float*)d_in[7];
    const float* pb  = (const float*)d_in[8];
    const float* mW  = (const float*)d_in[9];
    const float* mb  = (const float*)d_in[10];
    const float* slg = (const float*)d_in[11];
    const float* slb = (const float*)d_in[12];
    float* out = (float*)d_out;

    unsigned char *xh, *xl, *h0, *l0, *h1, *l1, *h2, *l2, *h3, *l3;
    cudaGetSymbolAddress((void**)&xh, g_xh);
    cudaGetSymbolAddress((void**)&xl, g_xl);
    cudaGetSymbolAddress((void**)&h0, g_h0);
    cudaGetSymbolAddress((void**)&l0, g_l0);
    cudaGetSymbolAddress((void**)&h1, g_h1);
    cudaGetSymbolAddress((void**)&l1, g_l1);
    cudaGetSymbolAddress((void**)&h2, g_h2);
    cudaGetSymbolAddress((void**)&l2, g_l2);
    cudaGetSymbolAddress((void**)&h3, g_h3);
    cudaGetSymbolAddress((void**)&l3, g_l3);

    cudaFuncSetAttribute(k_g2, cudaFuncAttributeMaxDynamicSharedMemorySize, SMEM_TOTAL);
    cudaFuncSetAttribute(k_gp, cudaFuncAttributeMaxDynamicSharedMemorySize, SMEM_TOTAL);
    cudaFuncSetAttribute(k_g1, cudaFuncAttributeMaxDynamicSharedMemorySize, SMEM_TOTAL);

    // G jobs (GCN): A-planes, w, PLAIN -> buf0 planes
    GJob G0 = { xh, xl, nullptr, nullptr, nullptr, nullptr,
                gb, nullptr, nullptr, nullptr, h0, l0, 0, 1, M_PLAIN, D, 0 };
    GJob G1 = { h1, l1, nullptr, nullptr, nullptr, nullptr,
                gb + D, nullptr, nullptr, nullptr, h0, l0, 1, 1, M_PLAIN, D, 0 };
    GJob G2 = { h1, l1, nullptr, nullptr, nullptr, nullptr,
                gb + 2 * D, nullptr, nullptr, nullptr, h0, l0, 2, 1, M_PLAIN, D, 0 };
    // S jobs (SAGE, pool fused as chunk 1)
    GJob S0 = { xh, xl, nullptr, nullptr, nullptr, nullptr,
                pb, nullptr, nullptr, nullptr, h2, l2, 3, 1, M_RELU, D, 0 };
    GJob S1 = { xh, xl, h2, l2, nullptr, nullptr,
                mb, nullptr, nullptr, nullptr, h3, l3, 4, 2, M_RELU, D, 0 };
    GJob S2 = { h3, l3, h3, l3, h3, l3,
                mb + D, slg, slb, nullptr, h2, l2, 6, 2, M_LN, D, 0 };
    GJob S3 = { h2, l2, h2, l2, h2, l2,
                mb + 2 * D, slg + D, slb + D, out, nullptr, nullptr,
                8, 2, M_LN, 2 * D, D };
    // P jobs
    PJob P0 = { h0, l0, h0, l0, glg,         glb,         nullptr, h1, l1, D, 0 };
    PJob P1 = { h0, l0, h1, l1, glg + D,     glb + D,     nullptr, h1, l1, D, 0 };
    PJob P2 = { h0, l0, h1, l1, glg + 2 * D, glb + 2 * D, out, nullptr, nullptr,
                2 * D, 0 };

    prep_all_kernel<<<170, 256>>>(nei, nbc, gW, pW, mW, x);

    k_g2<<<2 * GB, THREADS, SMEM_TOTAL>>>(G0, S0);       // step1: G0 | S0
    k_gp<<<GB + PB, THREADS, SMEM_TOTAL>>>(S1, P0);      // step2: S1 | P0
    k_g2<<<2 * GB, THREADS, SMEM_TOTAL>>>(G1, S2);       // step3: G1 | S2
    k_gp<<<GB + PB, THREADS, SMEM_TOTAL>>>(S3, P1);      // step4: S3 | P1
    k_g1<<<GB, THREADS, SMEM_TOTAL>>>(G2);               // step5: G2
    k_p<<<PB, THREADS>>>(P2);                            // step6: P2
}

// round 13
// speedup vs baseline: 1.0215x; 1.0215x over previous
#include <cuda_runtime.h>
#include <cuda_bf16.h>
#include <cstdint>

#define N_NODES 8192
#define D 128
#define KNBR 8
#define LN_EPS 1e-5f

#define M_PLAIN 0
#define M_RELU  1
#define M_LN    2

#define MTILE 64
#define THREADS 256
#define NBLK 256
// SMEM (bytes): Ah[64x128 bf16]=16K @0, Al @16384, Wh @32768, Wl @65536
#define OFF_AL 16384
#define OFF_WH 32768
#define OFF_WL 65536
#define SMEM_TOTAL 98304
#define WPLANE 32768           // one W plane [128 n][128 k] bf16
#define ROWB 256               // bytes per activation row per plane (128 bf16)

// ---------------- device globals (no allocation allowed) -------------------
__device__ __align__(16) unsigned char g_xh[N_NODES * ROWB];
__device__ __align__(16) unsigned char g_xl[N_NODES * ROWB];
__device__ __align__(16) unsigned char g_h0[N_NODES * ROWB];
__device__ __align__(16) unsigned char g_l0[N_NODES * ROWB];
__device__ __align__(16) unsigned char g_h1[N_NODES * ROWB];
__device__ __align__(16) unsigned char g_l1[N_NODES * ROWB];
__device__ __align__(16) unsigned char g_h2[N_NODES * ROWB];
__device__ __align__(16) unsigned char g_l2[N_NODES * ROWB];
__device__ __align__(16) unsigned char g_h3[N_NODES * ROWB];
__device__ __align__(16) unsigned char g_l3[N_NODES * ROWB];
__device__ float g_dinv[N_NODES];
__device__ int   g_kcnt[N_NODES];
__device__ __align__(16) int g_gn[N_NODES * KNBR];      // gcn kept list, pad=i
__device__ __align__(16) int g_pooln[N_NODES * KNBR];   // pool list, pad=first
__device__ float g_pmul[N_NODES];                       // 0 if leaf else 1
__device__ __align__(16) unsigned char g_wh[10 * WPLANE];
__device__ __align__(16) unsigned char g_wl[10 * WPLANE];
// grid barrier state (zero-init; returns to steady state each launch)
__device__ int g_cnt;
__device__ volatile int g_sense;

// ---------------- job descriptors -------------------------------------------
struct GJob {
    const unsigned char *ah, *al;     // A chunk-0 planes
    const unsigned char *ph, *pl;     // pool source planes (chunk 1)
    const unsigned char *rh, *rl;     // residual planes (LN)
    const float *bias, *lng, *lnb;
    float* outf;                      // fp32 out (or null)
    unsigned char *oh, *ol;           // hi/lo out (if outf null)
    int wchunk, nchunks, mode, ostride, ooff;
};
struct PJob {
    const unsigned char *nh, *nl;     // nxt planes
    const unsigned char *rh, *rl;     // res planes
    const float *lng, *lnb;
    float* outf;
    unsigned char *oh, *ol;
    int ostride, ooff;
};
struct Jobs {
    GJob G0, G1, G2, S0, S1, S2, S3;
    PJob P0, P1, P2;
    const int* nei; const int* nbc;
    const float *gW, *pW, *mW, *x;
};

// ---------------- helpers ---------------------------------------------------
__device__ __forceinline__ uint32_t smem_u32(const void* p) {
    uint32_t a;
    asm("{ .reg .u64 t; cvta.to.shared.u64 t, %1; cvt.u32.u64 %0, t; }"
        : "=r"(a) : "l"(p));
    return a;
}
__device__ __forceinline__ void ldsm4(uint32_t addr, uint32_t* r) {
    asm volatile("ldmatrix.sync.aligned.m8n8.x4.shared.b16 {%0,%1,%2,%3}, [%4];"
                 : "=r"(r[0]), "=r"(r[1]), "=r"(r[2]), "=r"(r[3]) : "r"(addr));
}
__device__ __forceinline__ void mma_bf16(float* d, const uint32_t* a,
                                         uint32_t b0, uint32_t b1) {
    asm volatile(
        "mma.sync.aligned.m16n8k16.row.col.f32.bf16.bf16.f32 "
        "{%0,%1,%2,%3}, {%4,%5,%6,%7}, {%8,%9}, {%0,%1,%2,%3};"
        : "+f"(d[0]), "+f"(d[1]), "+f"(d[2]), "+f"(d[3])
        : "r"(a[0]), "r"(a[1]), "r"(a[2]), "r"(a[3]), "r"(b0), "r"(b1));
}
__device__ __forceinline__ void bulk_g2s(uint32_t dst, const void* src,
                                         uint32_t bytes, uint32_t mbar) {
    asm volatile(
        "cp.async.bulk.shared::cluster.global.mbarrier::complete_tx::bytes "
        "[%0], [%1], %2, [%3];"
        :: "r"(dst), "l"(src), "r"(bytes), "r"(mbar) : "memory");
}
__device__ __forceinline__ void mbar_init(uint32_t a, uint32_t cnt) {
    asm volatile("mbarrier.init.shared.b64 [%0], %1;" :: "r"(a), "r"(cnt) : "memory");
}
__device__ __forceinline__ void mbar_expect_tx(uint32_t a, uint32_t tx) {
    asm volatile("mbarrier.arrive.expect_tx.shared.b64 _, [%0], %1;"
                 :: "r"(a), "r"(tx) : "memory");
}
__device__ __forceinline__ void mbar_wait(uint32_t a, uint32_t parity) {
    asm volatile(
        "{\n\t.reg .pred P;\n\t"
        "WL_%=:\n\t"
        "mbarrier.try_wait.parity.acquire.cta.shared::cta.b64 P, [%0], %1, 0x989680;\n\t"
        "@P bra.uni WD_%=;\n\t"
        "bra.uni WL_%=;\n\t"
        "WD_%=:\n\t}"
        :: "r"(a), "r"(parity) : "memory");
}
static __device__ __forceinline__ uint32_t bf2u(__nv_bfloat162 v) {
    return *reinterpret_cast<uint32_t*>(&v);
}
__device__ __forceinline__ void split8(const float* f, uint4& hi, uint4& lo) {
    __nv_bfloat16 h[8];
    float l[8];
#pragma unroll
    for (int e = 0; e < 8; ++e) {
        h[e] = __float2bfloat16(f[e]);
        l[e] = f[e] - __bfloat162float(h[e]);
    }
    hi.x = bf2u(__halves2bfloat162(h[0], h[1]));
    hi.y = bf2u(__halves2bfloat162(h[2], h[3]));
    hi.z = bf2u(__halves2bfloat162(h[4], h[5]));
    hi.w = bf2u(__halves2bfloat162(h[6], h[7]));
    lo.x = bf2u(__floats2bfloat162_rn(l[0], l[1]));
    lo.y = bf2u(__floats2bfloat162_rn(l[2], l[3]));
    lo.z = bf2u(__floats2bfloat162_rn(l[4], l[5]));
    lo.w = bf2u(__floats2bfloat162_rn(l[6], l[7]));
}
__device__ __forceinline__ void rec8(const unsigned char* hp,
                                     const unsigned char* lp,
                                     uint32_t off, float* v) {
    uint4 h = *(const uint4*)(hp + off);
    uint4 l = *(const uint4*)(lp + off);
    float2 p, q;
    p = __bfloat1622float2(*(const __nv_bfloat162*)&h.x);
    q = __bfloat1622float2(*(const __nv_bfloat162*)&l.x);
    v[0] = p.x + q.x; v[1] = p.y + q.y;
    p = __bfloat1622float2(*(const __nv_bfloat162*)&h.y);
    q = __bfloat1622float2(*(const __nv_bfloat162*)&l.y);
    v[2] = p.x + q.x; v[3] = p.y + q.y;
    p = __bfloat1622float2(*(const __nv_bfloat162*)&h.z);
    q = __bfloat1622float2(*(const __nv_bfloat162*)&l.z);
    v[4] = p.x + q.x; v[5] = p.y + q.y;
    p = __bfloat1622float2(*(const __nv_bfloat162*)&h.w);
    q = __bfloat1622float2(*(const __nv_bfloat162*)&l.w);
    v[6] = p.x + q.x; v[7] = p.y + q.y;
}
__device__ __forceinline__ uint32_t swz(int r, int ch) {
    return (uint32_t)r * ROWB + ((uint32_t)(ch ^ (r & 7)) << 4);
}

// ---------------- grid-wide barrier (sense-reversing) ----------------------
__device__ __forceinline__ void grid_bar(int phase) {
    __syncthreads();
    if (threadIdx.x == 0) {
        __threadfence();
        if (atomicAdd(&g_cnt, 1) == NBLK - 1) {
            g_cnt = 0;
            __threadfence();
            g_sense = phase;
        } else {
            while (g_sense != phase) __nanosleep(64);
        }
        __threadfence();
    }
    __syncthreads();
}

// ---------------- prep work (per-block unit c = blockIdx.x) ----------------
__device__ void prep_work(int c, const Jobs& JB) {
    int tid = threadIdx.x;
    if (c >= 170) return;
    if (c >= 42) {                       // x -> hi/lo swizzled planes
        int base = (c - 42) * 64;
#pragma unroll
        for (int it = 0; it < 4; ++it) {
            int idx = tid + it * 256;
            int r = base + (idx >> 4), ch = idx & 15;
            float f[8];
            float4 f0 = *(const float4*)&JB.x[r * D + ch * 8];
            float4 f1 = *(const float4*)&JB.x[r * D + ch * 8 + 4];
            f[0]=f0.x; f[1]=f0.y; f[2]=f0.z; f[3]=f0.w;
            f[4]=f1.x; f[5]=f1.y; f[6]=f1.z; f[7]=f1.w;
            uint4 hi, lo;
            split8(f, hi, lo);
            uint32_t off = swz(r, ch);
            *(uint4*)(g_xh + off) = hi;
            *(uint4*)(g_xl + off) = lo;
        }
        return;
    }
    if (c >= 10) {                       // graph tables
        int i = (c - 10) * 256 + tid;
        int cnt = JB.nbc[i];
        cnt = cnt > KNBR ? KNBR : (cnt < 0 ? 0 : cnt);
        int first = cnt > 0 ? JB.nei[i * KNBR] : 0;
#pragma unroll
        for (int k = 0; k < KNBR; ++k)
            g_pooln[i * KNBR + k] = k < cnt ? JB.nei[i * KNBR + k] : first;
        g_pmul[i] = cnt > 0 ? 1.f : 0.f;
        int kept[KNBR];
        int kc = 0;
        for (int k = 0; k < cnt; ++k) {
            int nb = JB.nei[i * KNBR + k];
            if (nb == i) continue;
            bool dup = false;
            for (int t = 0; t < kc; ++t) if (kept[t] == nb) dup = true;
            if (!dup) kept[kc++] = nb;
        }
#pragma unroll
        for (int k = 0; k < KNBR; ++k)
            g_gn[i * KNBR + k] = k < kc ? kept[k] : i;
        g_kcnt[i] = kc;
        g_dinv[i] = rsqrtf((float)(kc + 1));
        return;
    }
    // W chunks 0-9
    const float* src;
    int stride, coloff;
    if (c < 3)       { src = JB.gW + c * 16384; stride = 128; coloff = 0; }
    else if (c == 3) { src = JB.pW;             stride = 128; coloff = 0; }
    else { int l = (c - 4) >> 1, h = (c - 4) & 1;
           src = JB.mW + l * 32768; stride = 256; coloff = h * 128; }
    unsigned char* wh = g_wh + c * WPLANE;
    unsigned char* wl = g_wl + c * WPLANE;
    for (int i = tid; i < 2048; i += 256) {
        int n = i >> 4, ch = i & 15;
        float f[8];
#pragma unroll
        for (int e = 0; e < 8; ++e) f[e] = src[n * stride + coloff + ch * 8 + e];
        uint4 hi, lo;
        split8(f, hi, lo);
        uint32_t off = swz(n, ch);
        *(uint4*)(wh + off) = hi;
        *(uint4*)(wl + off) = lo;
    }
}

// one pass: acc += A(aB) @ W(wB)^T for this warp's 32x32 pair tile
__device__ __forceinline__ void gemm_pass(uint32_t aB, uint32_t wB,
                                          int rowA0, int rowA1,
                                          int rowB0, int rowB1, int lhalf,
                                          float acc[2][4][4]) {
#pragma unroll
    for (int ks = 0; ks < 8; ++ks) {
        const int ch = ks * 2 + lhalf;
        uint32_t a0[4], a1[4], b0[4], b1[4];
        ldsm4(aB + swz(rowA0, ch), a0);
        ldsm4(aB + swz(rowA1, ch), a1);
        ldsm4(wB + swz(rowB0, ch), b0);
        ldsm4(wB + swz(rowB1, ch), b1);
        mma_bf16(acc[0][0], a0, b0[0], b0[2]);
        mma_bf16(acc[0][1], a0, b0[1], b0[3]);
        mma_bf16(acc[0][2], a0, b1[0], b1[2]);
        mma_bf16(acc[0][3], a0, b1[1], b1[3]);
        mma_bf16(acc[1][0], a1, b0[0], b0[2]);
        mma_bf16(acc[1][1], a1, b0[1], b0[3]);
        mma_bf16(acc[1][2], a1, b1[0], b1[2]);
        mma_bf16(acc[1][3], a1, b1[1], b1[3]);
    }
}

// ---------------- GEMM body: out = [A | pool(psrc)] @ W^T + b --------------
// hi/lo: D = Ah@Wh + Al@Wh + Ah@Wl; Wh+Wl both resident (R11 scheme).
__device__ void gemm_body(const GJob& J, int bid, char* smem_raw,
                          uint32_t mbar, int& ph) {
    const uint32_t sbase = smem_u32(smem_raw);
    const int tid = threadIdx.x, wid = tid >> 5, lane = tid & 31;
    const int wm = wid & 1, wn = wid >> 1;
    const int m0 = bid * MTILE;

    float acc[2][4][4];
#pragma unroll
    for (int i = 0; i < 2; ++i)
#pragma unroll
        for (int j = 0; j < 4; ++j)
#pragma unroll
            for (int r = 0; r < 4; ++r) acc[i][j][r] = 0.f;

    const int lrow = lane & 15, lhalf = lane >> 4;
    const int rowA0 = wm * 32 + lrow, rowA1 = rowA0 + 16;
    const int rowB0 = wn * 32 + lrow, rowB1 = rowB0 + 16;

    for (int c = 0; c < J.nchunks; ++c) {
        if (c) __syncthreads();
        if (tid == 0) {
            mbar_expect_tx(mbar, 2 * WPLANE + (c == 0 ? 32768u : 0u));
            bulk_g2s(sbase + OFF_WH, g_wh + (J.wchunk + c) * WPLANE, WPLANE, mbar);
            bulk_g2s(sbase + OFF_WL, g_wl + (J.wchunk + c) * WPLANE, WPLANE, mbar);
            if (c == 0) {
                bulk_g2s(sbase,          J.ah + (size_t)m0 * ROWB, 16384, mbar);
                bulk_g2s(sbase + OFF_AL, J.al + (size_t)m0 * ROWB, 16384, mbar);
            }
        }
        if (c == 1) {
            // fused max-pool gather into A smem planes (hi/lo, swizzled)
            for (int i = tid; i < 1024; i += THREADS) {
                int r = i >> 4, ch = i & 15;
                int node = m0 + r;
                const int4* nl = (const int4*)(g_pooln + node * KNBR);
                int4 na = nl[0], nb = nl[1];
                float pm = g_pmul[node];
                int idx[8] = { na.x, na.y, na.z, na.w, nb.x, nb.y, nb.z, nb.w };
                float mv[8], tv[8];
                rec8(J.ph, J.pl, swz(idx[0], ch), mv);
#pragma unroll
                for (int t = 1; t < 8; ++t) {
                    rec8(J.ph, J.pl, swz(idx[t], ch), tv);
#pragma unroll
                    for (int e = 0; e < 8; ++e) mv[e] = fmaxf(mv[e], tv[e]);
                }
#pragma unroll
                for (int e = 0; e < 8; ++e) mv[e] *= pm;
                uint4 hi, lo;
                split8(mv, hi, lo);
                uint32_t off = swz(r, ch);
                *(uint4*)(smem_raw + off) = hi;
                *(uint4*)(smem_raw + OFF_AL + off) = lo;
            }
        }
        __syncthreads();
        mbar_wait(mbar, ph & 1); ph++;
        gemm_pass(sbase,          sbase + OFF_WH, rowA0, rowA1, rowB0, rowB1, lhalf, acc);
        gemm_pass(sbase + OFF_AL, sbase + OFF_WH, rowA0, rowA1, rowB0, rowB1, lhalf, acc);
        gemm_pass(sbase,          sbase + OFF_WL, rowA0, rowA1, rowB0, rowB1, lhalf, acc);
    }

    // ---- epilogue: fragments -> sC fp32 (bias [+relu]) -> per-row finish --
    const int frow = lane >> 2, fcol = 2 * (lane & 3);
    float* sC = (float*)smem_raw;                 // [64][132]
    __syncthreads();
#pragma unroll
    for (int i = 0; i < 2; ++i)
#pragma unroll
        for (int j = 0; j < 4; ++j) {
            int ncol = wn * 32 + j * 8 + fcol;
            float2 bj = *(const float2*)&J.bias[ncol];
            int r = wm * 32 + i * 16 + frow;
            float v0 = acc[i][j][0] + bj.x, v1 = acc[i][j][1] + bj.y;
            float v2 = acc[i][j][2] + bj.x, v3 = acc[i][j][3] + bj.y;
            if (J.mode != M_PLAIN) {
                v0 = fmaxf(v0, 0.f); v1 = fmaxf(v1, 0.f);
                v2 = fmaxf(v2, 0.f); v3 = fmaxf(v3, 0.f);
            }
            sC[r * 132 + ncol]           = v0;
            sC[r * 132 + ncol + 1]       = v1;
            sC[(r + 8) * 132 + ncol]     = v2;
            sC[(r + 8) * 132 + ncol + 1] = v3;
        }
    __syncthreads();

    {
        const int row = tid >> 2, q = tid & 3;     // 4 threads/row, 64 rows
        const int m = m0 + row;
        float mean = 0.f, rstd = 1.f;
        if (J.mode == M_LN) {
            float s = 0.f, ss = 0.f;
#pragma unroll
            for (int cq = 0; cq < 4; ++cq) {
                float r8[8];
                rec8(J.rh, J.rl, swz(m, q * 4 + cq), r8);
                float* cp = &sC[row * 132 + q * 32 + cq * 8];
                float4 a0 = *(float4*)cp, a1 = *(float4*)(cp + 4);
                a0.x += r8[0]; a0.y += r8[1]; a0.z += r8[2]; a0.w += r8[3];
                a1.x += r8[4]; a1.y += r8[5]; a1.z += r8[6]; a1.w += r8[7];
                s  += a0.x + a0.y + a0.z + a0.w + a1.x + a1.y + a1.z + a1.w;
                ss += a0.x * a0.x + a0.y * a0.y + a0.z * a0.z + a0.w * a0.w +
                      a1.x * a1.x + a1.y * a1.y + a1.z * a1.z + a1.w * a1.w;
                *(float4*)cp = a0;
                *(float4*)(cp + 4) = a1;
            }
#pragma unroll
            for (int off = 1; off < 4; off <<= 1) {
                s  += __shfl_xor_sync(0xffffffffu, s,  off);
                ss += __shfl_xor_sync(0xffffffffu, ss, off);
            }
            mean = s * (1.0f / 128.0f);
            rstd = rsqrtf(ss * (1.0f / 128.0f) - mean * mean + LN_EPS);
        }
#pragma unroll
        for (int cq = 0; cq < 4; ++cq) {
            int col = q * 32 + cq * 8;
            float* cp = &sC[row * 132 + col];
            float v[8];
            *(float4*)&v[0] = *(float4*)cp;
            *(float4*)&v[4] = *(float4*)(cp + 4);
            if (J.mode == M_LN) {
                float4 g0 = *(const float4*)&J.lng[col];
                float4 g1 = *(const float4*)&J.lng[col + 4];
                float4 o0 = *(const float4*)&J.lnb[col];
                float4 o1 = *(const float4*)&J.lnb[col + 4];
                v[0] = (v[0] - mean) * rstd * g0.x + o0.x;
                v[1] = (v[1] - mean) * rstd * g0.y + o0.y;
                v[2] = (v[2] - mean) * rstd * g0.z + o0.z;
                v[3] = (v[3] - mean) * rstd * g0.w + o0.w;
                v[4] = (v[4] - mean) * rstd * g1.x + o1.x;
                v[5] = (v[5] - mean) * rstd * g1.y + o1.y;
                v[6] = (v[6] - mean) * rstd * g1.z + o1.z;
                v[7] = (v[7] - mean) * rstd * g1.w + o1.w;
            }
            if (J.outf) {
                *(float4*)&J.outf[(size_t)m * J.ostride + J.ooff + col]     = *(float4*)&v[0];
                *(float4*)&J.outf[(size_t)m * J.ostride + J.ooff + col + 4] = *(float4*)&v[4];
            } else {
                uint4 hi, lo;
                split8(v, hi, lo);
                uint32_t off = swz(m, q * 4 + cq);
                *(uint4*)(J.oh + off) = hi;
                *(uint4*)(J.ol + off) = lo;
            }
        }
    }
}

// ---------------- prop body: 64 nodes/block, 2 nodes/warp, 16-lane rows ----
__device__ void prop_body(const PJob& P, int blk) {
    const int lane = threadIdx.x & 31, wid = threadIdx.x >> 5;
    const int half = lane >> 4, ch = lane & 15;
    for (int t = 0; t < 4; ++t) {
        const int i = blk * 64 + t * 16 + wid * 2 + half;
        const float di = g_dinv[i];
        float a[8], acc[8];
        rec8(P.nh, P.nl, swz(i, ch), a);
#pragma unroll
        for (int e = 0; e < 8; ++e) acc[e] = di * a[e];
        const int kc = g_kcnt[i];
        const int* kn = g_gn + i * KNBR;
        for (int k = 0; k < kc; ++k) {
            int j = kn[k];
            float dj = g_dinv[j];
            rec8(P.nh, P.nl, swz(j, ch), a);
#pragma unroll
            for (int e = 0; e < 8; ++e) acc[e] += dj * a[e];
        }
        rec8(P.rh, P.rl, swz(i, ch), a);           // residual
        float v[8];
        float s = 0.f, ss = 0.f;
#pragma unroll
        for (int e = 0; e < 8; ++e) {
            v[e] = fmaxf(di * acc[e], 0.f) + a[e];
            s += v[e]; ss += v[e] * v[e];
        }
#pragma unroll
        for (int off = 1; off < 16; off <<= 1) {
            s  += __shfl_xor_sync(0xffffffffu, s,  off);
            ss += __shfl_xor_sync(0xffffffffu, ss, off);
        }
        float mean = s * (1.0f / 128.0f);
        float rstd = rsqrtf(ss * (1.0f / 128.0f) - mean * mean + LN_EPS);
        float4 g0 = *(const float4*)&P.lng[ch * 8];
        float4 g1 = *(const float4*)&P.lng[ch * 8 + 4];
        float4 o0 = *(const float4*)&P.lnb[ch * 8];
        float4 o1 = *(const float4*)&P.lnb[ch * 8 + 4];
        v[0] = (v[0] - mean) * rstd * g0.x + o0.x;
        v[1] = (v[1] - mean) * rstd * g0.y + o0.y;
        v[2] = (v[2] - mean) * rstd * g0.z + o0.z;
        v[3] = (v[3] - mean) * rstd * g0.w + o0.w;
        v[4] = (v[4] - mean) * rstd * g1.x + o1.x;
        v[5] = (v[5] - mean) * rstd * g1.y + o1.y;
        v[6] = (v[6] - mean) * rstd * g1.z + o1.z;
        v[7] = (v[7] - mean) * rstd * g1.w + o1.w;
        if (P.outf) {
            *(float4*)&P.outf[(size_t)i * P.ostride + P.ooff + ch * 8]     = *(float4*)&v[0];
            *(float4*)&P.outf[(size_t)i * P.ostride + P.ooff + ch * 8 + 4] = *(float4*)&v[4];
        } else {
            uint4 hi, lo;
            split8(v, hi, lo);
            uint32_t off = swz(i, ch);
            *(uint4*)(P.oh + off) = hi;
            *(uint4*)(P.ol + off) = lo;
        }
    }
}

#define GB (N_NODES / MTILE)    // 128 gemm tiles per job

// ---------------- persistent mega-kernel ------------------------------------
__global__ __launch_bounds__(THREADS, 2) void mega_kernel(Jobs JB) {
    extern __shared__ __align__(256) char smem_raw[];
    __shared__ __align__(8) uint64_t s_mbar;
    const uint32_t mbar = smem_u32(&s_mbar);
    if (threadIdx.x == 0) mbar_init(mbar, 1);
    __syncthreads();
    int ph = 0;
    const int b = blockIdx.x;

    // stage 0: prep (W split, graph tables, x conversion)
    prep_work(b, JB);
    grid_bar(1);
    // stage 1: G0 | S0
    if (b < GB) gemm_body(JB.G0, b, smem_raw, mbar, ph);
    else        gemm_body(JB.S0, b - GB, smem_raw, mbar, ph);
    grid_bar(2);
    // stage 2: S1 | P0
    if (b < GB) gemm_body(JB.S1, b, smem_raw, mbar, ph);
    else        prop_body(JB.P0, b - GB);
    grid_bar(3);
    // stage 3: G1 | S2
    if (b < GB) gemm_body(JB.G1, b, smem_raw, mbar, ph);
    else        gemm_body(JB.S2, b - GB, smem_raw, mbar, ph);
    grid_bar(4);
    // stage 4: S3 | P1
    if (b < GB) gemm_body(JB.S3, b, smem_raw, mbar, ph);
    else        prop_body(JB.P1, b - GB);
    grid_bar(5);
    // stage 5: G2
    if (b < GB) gemm_body(JB.G2, b, smem_raw, mbar, ph);
    grid_bar(6);
    // stage 6: P2
    if (b < GB) prop_body(JB.P2, b);
}

// ---------------- driver ----------------------------------------------------
extern "C" void kernel_launch(void* const* d_in, const int* in_sizes, int n_in,
                              void* d_out, int out_size) {
    const float* x   = (const float*)d_in[0];
    const int*   nei = (const int*)  d_in[1];
    const int*   nbc = (const int*)  d_in[2];
    const float* gW  = (const float*)d_in[3];
    const float* gb  = (const float*)d_in[4];
    const float* glg = (const float*)d_in[5];
    const float* glb = (const float*)d_in[6];
    const float* pW  = (const float*)d_in[7];
    const float* pb  = (const float*)d_in[8];
    const float* mW  = (const float*)d_in[9];
    const float* mb  = (const float*)d_in[10];
    const float* slg = (const float*)d_in[11];
    const float* slb = (const float*)d_in[12];
    float* out = (float*)d_out;

    unsigned char *xh, *xl, *h0, *l0, *h1, *l1, *h2, *l2, *h3, *l3;
    cudaGetSymbolAddress((void**)&xh, g_xh);
    cudaGetSymbolAddress((void**)&xl, g_xl);
    cudaGetSymbolAddress((void**)&h0, g_h0);
    cudaGetSymbolAddress((void**)&l0, g_l0);
    cudaGetSymbolAddress((void**)&h1, g_h1);
    cudaGetSymbolAddress((void**)&l1, g_l1);
    cudaGetSymbolAddress((void**)&h2, g_h2);
    cudaGetSymbolAddress((void**)&l2, g_l2);
    cudaGetSymbolAddress((void**)&h3, g_h3);
    cudaGetSymbolAddress((void**)&l3, g_l3);

    cudaFuncSetAttribute(mega_kernel,
                         cudaFuncAttributeMaxDynamicSharedMemorySize, SMEM_TOTAL);

    Jobs JB;
    // G jobs (GCN): PLAIN -> buf0 planes
    JB.G0 = { xh, xl, nullptr, nullptr, nullptr, nullptr,
              gb, nullptr, nullptr, nullptr, h0, l0, 0, 1, M_PLAIN, D, 0 };
    JB.G1 = { h1, l1, nullptr, nullptr, nullptr, nullptr,
              gb + D, nullptr, nullptr, nullptr, h0, l0, 1, 1, M_PLAIN, D, 0 };
    JB.G2 = { h1, l1, nullptr, nullptr, nullptr, nullptr,
              gb + 2 * D, nullptr, nullptr, nullptr, h0, l0, 2, 1, M_PLAIN, D, 0 };
    // S jobs (SAGE, pool fused as chunk 1)
    JB.S0 = { xh, xl, nullptr, nullptr, nullptr, nullptr,
              pb, nullptr, nullptr, nullptr, h2, l2, 3, 1, M_RELU, D, 0 };
    JB.S1 = { xh, xl, h2, l2, nullptr, nullptr,
              mb, nullptr, nullptr, nullptr, h3, l3, 4, 2, M_RELU, D, 0 };
    JB.S2 = { h3, l3, h3, l3, h3, l3,
              mb + D, slg, slb, nullptr, h2, l2, 6, 2, M_LN, D, 0 };
    JB.S3 = { h2, l2, h2, l2, h2, l2,
              mb + 2 * D, slg + D, slb + D, out, nullptr, nullptr,
              8, 2, M_LN, 2 * D, D };
    // P jobs
    JB.P0 = { h0, l0, h0, l0, glg,         glb,         nullptr, h1, l1, D, 0 };
    JB.P1 = { h0, l0, h1, l1, glg + D,     glb + D,     nullptr, h1, l1, D, 0 };
    JB.P2 = { h0, l0, h1, l1, glg + 2 * D, glb + 2 * D, out, nullptr, nullptr,
              2 * D, 0 };
    JB.nei = nei; JB.nbc = nbc;
    JB.gW = gW; JB.pW = pW; JB.mW = mW; JB.x = x;

    mega_kernel<<<NBLK, THREADS, SMEM_TOTAL>>>(JB);
}

// round 14
// speedup vs baseline: 1.5835x; 1.5502x over previous
#include <cuda_runtime.h>
#include <cuda_fp16.h>
#include <cstdint>

#define N_NODES 8192
#define D 128
#define KNBR 8
#define LN_EPS 1e-5f

#define M_PLAIN 0
#define M_RELU  1
#define M_LN    2

#define MTILE 64
#define THREADS 256
// SMEM (bytes): A[64x128 fp16]=16K @0, W[128x128 fp16]=32K @16384
#define OFF_W 16384
#define SMEM_TOTAL 49152
#define WPLANE 32768           // one W chunk [128 n][128 k] fp16
#define ROWB 256               // bytes per activation row (128 fp16)

// ---------------- device globals (no allocation allowed) -------------------
// activation planes: fp16, swizzled rows (chunk ch at ((ch^(r&7))<<4))
__device__ __align__(16) unsigned char g_x[N_NODES * ROWB];
__device__ __align__(16) unsigned char g_p0[N_NODES * ROWB];
__device__ __align__(16) unsigned char g_p1[N_NODES * ROWB];
__device__ __align__(16) unsigned char g_p2[N_NODES * ROWB];
__device__ __align__(16) unsigned char g_p3[N_NODES * ROWB];
__device__ float g_dinv[N_NODES];
__device__ int   g_kcnt[N_NODES];
__device__ __align__(16) int g_gn[N_NODES * KNBR];      // gcn kept list, pad=i
__device__ __align__(16) int g_pooln[N_NODES * KNBR];   // pool list, pad=first
__device__ float g_pmul[N_NODES];                       // 0 if leaf else 1
// pre-converted, pre-swizzled weights: 10 chunks of [128 n][128 k] fp16
__device__ __align__(16) unsigned char g_w[10 * WPLANE];

// ---------------- job descriptors -------------------------------------------
struct GJob {
    const unsigned char* a;           // A chunk-0 plane
    const unsigned char* p;           // pool source plane (chunk 1)
    const unsigned char* r;           // residual plane (LN)
    const float *bias, *lng, *lnb;
    float* outf;                      // fp32 out (or null)
    unsigned char* o;                 // fp16 plane out (if outf null)
    int wchunk, nchunks, mode, ostride, ooff;
};
struct PJob {
    const unsigned char* n;           // nxt plane
    const unsigned char* r;           // res plane
    const float *lng, *lnb;
    float* outf;
    unsigned char* o;
    int ostride, ooff;
};

// ---------------- helpers ---------------------------------------------------
__device__ __forceinline__ uint32_t smem_u32(const void* p) {
    uint32_t a;
    asm("{ .reg .u64 t; cvta.to.shared.u64 t, %1; cvt.u32.u64 %0, t; }"
        : "=r"(a) : "l"(p));
    return a;
}
__device__ __forceinline__ void ldsm4(uint32_t addr, uint32_t* r) {
    asm volatile("ldmatrix.sync.aligned.m8n8.x4.shared.b16 {%0,%1,%2,%3}, [%4];"
                 : "=r"(r[0]), "=r"(r[1]), "=r"(r[2]), "=r"(r[3]) : "r"(addr));
}
__device__ __forceinline__ void mma_fp16(float* d, const uint32_t* a,
                                         uint32_t b0, uint32_t b1) {
    asm volatile(
        "mma.sync.aligned.m16n8k16.row.col.f32.f16.f16.f32 "
        "{%0,%1,%2,%3}, {%4,%5,%6,%7}, {%8,%9}, {%0,%1,%2,%3};"
        : "+f"(d[0]), "+f"(d[1]), "+f"(d[2]), "+f"(d[3])
        : "r"(a[0]), "r"(a[1]), "r"(a[2]), "r"(a[3]), "r"(b0), "r"(b1));
}
__device__ __forceinline__ void bulk_g2s(uint32_t dst, const void* src,
                                         uint32_t bytes, uint32_t mbar) {
    asm volatile(
        "cp.async.bulk.shared::cluster.global.mbarrier::complete_tx::bytes "
        "[%0], [%1], %2, [%3];"
        :: "r"(dst), "l"(src), "r"(bytes), "r"(mbar) : "memory");
}
__device__ __forceinline__ void mbar_init(uint32_t a, uint32_t cnt) {
    asm volatile("mbarrier.init.shared.b64 [%0], %1;" :: "r"(a), "r"(cnt) : "memory");
}
__device__ __forceinline__ void mbar_expect_tx(uint32_t a, uint32_t tx) {
    asm volatile("mbarrier.arrive.expect_tx.shared.b64 _, [%0], %1;"
                 :: "r"(a), "r"(tx) : "memory");
}
__device__ __forceinline__ void mbar_wait(uint32_t a, uint32_t parity) {
    asm volatile(
        "{\n\t.reg .pred P;\n\t"
        "WL_%=:\n\t"
        "mbarrier.try_wait.parity.acquire.cta.shared::cta.b64 P, [%0], %1, 0x989680;\n\t"
        "@P bra.uni WD_%=;\n\t"
        "bra.uni WL_%=;\n\t"
        "WD_%=:\n\t}"
        :: "r"(a), "r"(parity) : "memory");
}
static __device__ __forceinline__ uint32_t h2u(__half2 v) {
    return *reinterpret_cast<uint32_t*>(&v);
}
// pack 8 fp32 -> uint4 of fp16 pairs
__device__ __forceinline__ uint4 pack8(const float* f) {
    uint4 o;
    o.x = h2u(__floats2half2_rn(f[0], f[1]));
    o.y = h2u(__floats2half2_rn(f[2], f[3]));
    o.z = h2u(__floats2half2_rn(f[4], f[5]));
    o.w = h2u(__floats2half2_rn(f[6], f[7]));
    return o;
}
// read one swizzled 16B chunk -> 8 fp32
__device__ __forceinline__ void rec8(const unsigned char* p, uint32_t off,
                                     float* v) {
    uint4 h = *(const uint4*)(p + off);
    float2 t;
    t = __half22float2(*(const __half2*)&h.x); v[0] = t.x; v[1] = t.y;
    t = __half22float2(*(const __half2*)&h.y); v[2] = t.x; v[3] = t.y;
    t = __half22float2(*(const __half2*)&h.z); v[4] = t.x; v[5] = t.y;
    t = __half22float2(*(const __half2*)&h.w); v[6] = t.x; v[7] = t.y;
}
__device__ __forceinline__ uint32_t swz(int r, int ch) {
    return (uint32_t)r * ROWB + ((uint32_t)(ch ^ (r & 7)) << 4);
}
__device__ __forceinline__ uint32_t hmax2u(uint32_t a, uint32_t b) {
    __half2 r = __hmax2(*reinterpret_cast<__half2*>(&a),
                        *reinterpret_cast<__half2*>(&b));
    return h2u(r);
}

// ---------------- prep: W cvt (0-9), graph (10-41), x cvt (42-105) ---------
__global__ void prep_all_kernel(const int* __restrict__ neigh,
                                const int* __restrict__ nbrc,
                                const float* __restrict__ gW,
                                const float* __restrict__ pW,
                                const float* __restrict__ mW,
                                const float* __restrict__ x) {
    int c = blockIdx.x, tid = threadIdx.x;
    if (c >= 42) {                       // x -> fp16 swizzled plane
        int base = (c - 42) * 128;
#pragma unroll
        for (int it = 0; it < 8; ++it) {
            int idx = tid + it * 256;
            int r = base + (idx >> 4), ch = idx & 15;
            float f[8];
            float4 f0 = *(const float4*)&x[r * D + ch * 8];
            float4 f1 = *(const float4*)&x[r * D + ch * 8 + 4];
            f[0]=f0.x; f[1]=f0.y; f[2]=f0.z; f[3]=f0.w;
            f[4]=f1.x; f[5]=f1.y; f[6]=f1.z; f[7]=f1.w;
            *(uint4*)(g_x + swz(r, ch)) = pack8(f);
        }
        return;
    }
    if (c >= 10) {                       // graph tables
        int i = (c - 10) * 256 + tid;
        int cnt = nbrc[i];
        cnt = cnt > KNBR ? KNBR : (cnt < 0 ? 0 : cnt);
        int first = cnt > 0 ? neigh[i * KNBR] : 0;
#pragma unroll
        for (int k = 0; k < KNBR; ++k)
            g_pooln[i * KNBR + k] = k < cnt ? neigh[i * KNBR + k] : first;
        g_pmul[i] = cnt > 0 ? 1.f : 0.f;
        int kept[KNBR];
        int kc = 0;
        for (int k = 0; k < cnt; ++k) {
            int nb = neigh[i * KNBR + k];
            if (nb == i) continue;
            bool dup = false;
            for (int t = 0; t < kc; ++t) if (kept[t] == nb) dup = true;
            if (!dup) kept[kc++] = nb;
        }
#pragma unroll
        for (int k = 0; k < KNBR; ++k)
            g_gn[i * KNBR + k] = k < kc ? kept[k] : i;
        g_kcnt[i] = kc;
        g_dinv[i] = rsqrtf((float)(kc + 1));
        return;
    }
    // W chunks
    const float* src;
    int stride, coloff;
    if (c < 3)       { src = gW + c * 16384; stride = 128; coloff = 0; }
    else if (c == 3) { src = pW;             stride = 128; coloff = 0; }
    else { int l = (c - 4) >> 1, h = (c - 4) & 1;
           src = mW + l * 32768; stride = 256; coloff = h * 128; }
    unsigned char* w = g_w + c * WPLANE;
    for (int i = tid; i < 2048; i += 256) {
        int n = i >> 4, ch = i & 15;
        float f[8];
#pragma unroll
        for (int e = 0; e < 8; ++e) f[e] = src[n * stride + coloff + ch * 8 + e];
        *(uint4*)(w + swz(n, ch)) = pack8(f);
    }
}

// ---------------- GEMM body: out = [A | pool(psrc)] @ W^T + b --------------
// single-pass fp16, fp32 accum. 8 warps, warp tile 32x32.
__device__ void gemm_body(const GJob& J, int bid, char* smem_raw) {
    __shared__ __align__(8) uint64_t s_mbar;
    const uint32_t sbase = smem_u32(smem_raw);
    const uint32_t mbar = smem_u32(&s_mbar);
    const int tid = threadIdx.x, wid = tid >> 5, lane = tid & 31;
    const int wm = wid & 1, wn = wid >> 1;
    const int m0 = bid * MTILE;

    if (tid == 0) mbar_init(mbar, 1);
    __syncthreads();

    float acc[2][4][4];
#pragma unroll
    for (int i = 0; i < 2; ++i)
#pragma unroll
        for (int j = 0; j < 4; ++j)
#pragma unroll
            for (int r = 0; r < 4; ++r) acc[i][j][r] = 0.f;

    const int lrow = lane & 15, lhalf = lane >> 4;
    const int rowA0 = wm * 32 + lrow, rowA1 = rowA0 + 16;
    const int rowB0 = wn * 32 + lrow, rowB1 = rowB0 + 16;

    for (int c = 0; c < J.nchunks; ++c) {
        if (c) __syncthreads();
        if (tid == 0) {
            mbar_expect_tx(mbar, WPLANE + (c == 0 ? 16384u : 0u));
            bulk_g2s(sbase + OFF_W, g_w + (J.wchunk + c) * WPLANE, WPLANE, mbar);
            if (c == 0)
                bulk_g2s(sbase, J.a + (size_t)m0 * ROWB, 16384, mbar);
        }
        if (c == 1) {
            // fused max-pool gather into A smem (fp16, swizzled, hmax2)
            for (int i = tid; i < 1024; i += THREADS) {
                int r = i >> 4, ch = i & 15;
                int node = m0 + r;
                const int4* nl = (const int4*)(g_pooln + node * KNBR);
                int4 na = nl[0], nb = nl[1];
                int idx[8] = { na.x, na.y, na.z, na.w, nb.x, nb.y, nb.z, nb.w };
                uint4 mv = *(const uint4*)(J.p + swz(idx[0], ch));
#pragma unroll
                for (int t = 1; t < 8; ++t) {
                    uint4 tv = *(const uint4*)(J.p + swz(idx[t], ch));
                    mv.x = hmax2u(mv.x, tv.x);
                    mv.y = hmax2u(mv.y, tv.y);
                    mv.z = hmax2u(mv.z, tv.z);
                    mv.w = hmax2u(mv.w, tv.w);
                }
                if (g_pmul[node] == 0.f) mv = make_uint4(0, 0, 0, 0);
                *(uint4*)(smem_raw + swz(r, ch)) = mv;
            }
        }
        __syncthreads();
        mbar_wait(mbar, c & 1);

#pragma unroll
        for (int ks = 0; ks < 8; ++ks) {
            const int ch = ks * 2 + lhalf;
            uint32_t a0[4], a1[4], b0[4], b1[4];
            ldsm4(sbase + swz(rowA0, ch), a0);
            ldsm4(sbase + swz(rowA1, ch), a1);
            ldsm4(sbase + OFF_W + swz(rowB0, ch), b0);
            ldsm4(sbase + OFF_W + swz(rowB1, ch), b1);
            mma_fp16(acc[0][0], a0, b0[0], b0[2]);
            mma_fp16(acc[0][1], a0, b0[1], b0[3]);
            mma_fp16(acc[0][2], a0, b1[0], b1[2]);
            mma_fp16(acc[0][3], a0, b1[1], b1[3]);
            mma_fp16(acc[1][0], a1, b0[0], b0[2]);
            mma_fp16(acc[1][1], a1, b0[1], b0[3]);
            mma_fp16(acc[1][2], a1, b1[0], b1[2]);
            mma_fp16(acc[1][3], a1, b1[1], b1[3]);
        }
    }

    // ---- epilogue: fragments -> sC fp32 (bias [+relu]) -> per-row finish --
    const int frow = lane >> 2, fcol = 2 * (lane & 3);
    float* sC = (float*)smem_raw;                 // [64][132]
    __syncthreads();
#pragma unroll
    for (int i = 0; i < 2; ++i)
#pragma unroll
        for (int j = 0; j < 4; ++j) {
            int ncol = wn * 32 + j * 8 + fcol;
            float2 bj = *(const float2*)&J.bias[ncol];
            int r = wm * 32 + i * 16 + frow;
            float v0 = acc[i][j][0] + bj.x, v1 = acc[i][j][1] + bj.y;
            float v2 = acc[i][j][2] + bj.x, v3 = acc[i][j][3] + bj.y;
            if (J.mode != M_PLAIN) {
                v0 = fmaxf(v0, 0.f); v1 = fmaxf(v1, 0.f);
                v2 = fmaxf(v2, 0.f); v3 = fmaxf(v3, 0.f);
            }
            sC[r * 132 + ncol]           = v0;
            sC[r * 132 + ncol + 1]       = v1;
            sC[(r + 8) * 132 + ncol]     = v2;
            sC[(r + 8) * 132 + ncol + 1] = v3;
        }
    __syncthreads();

    {
        const int row = tid >> 2, q = tid & 3;     // 4 threads/row, 64 rows
        const int m = m0 + row;
        float mean = 0.f, rstd = 1.f;
        if (J.mode == M_LN) {
            float s = 0.f, ss = 0.f;
#pragma unroll
            for (int cq = 0; cq < 4; ++cq) {
                float r8[8];
                rec8(J.r, swz(m, q * 4 + cq), r8);
                float* cp = &sC[row * 132 + q * 32 + cq * 8];
                float4 a0 = *(float4*)cp, a1 = *(float4*)(cp + 4);
                a0.x += r8[0]; a0.y += r8[1]; a0.z += r8[2]; a0.w += r8[3];
                a1.x += r8[4]; a1.y += r8[5]; a1.z += r8[6]; a1.w += r8[7];
                s  += a0.x + a0.y + a0.z + a0.w + a1.x + a1.y + a1.z + a1.w;
                ss += a0.x * a0.x + a0.y * a0.y + a0.z * a0.z + a0.w * a0.w +
                      a1.x * a1.x + a1.y * a1.y + a1.z * a1.z + a1.w * a1.w;
                *(float4*)cp = a0;
                *(float4*)(cp + 4) = a1;
            }
#pragma unroll
            for (int off = 1; off < 4; off <<= 1) {
                s  += __shfl_xor_sync(0xffffffffu, s,  off);
                ss += __shfl_xor_sync(0xffffffffu, ss, off);
            }
            mean = s * (1.0f / 128.0f);
            rstd = rsqrtf(ss * (1.0f / 128.0f) - mean * mean + LN_EPS);
        }
#pragma unroll
        for (int cq = 0; cq < 4; ++cq) {
            int col = q * 32 + cq * 8;
            float* cp = &sC[row * 132 + col];
            float v[8];
            *(float4*)&v[0] = *(float4*)cp;
            *(float4*)&v[4] = *(float4*)(cp + 4);
            if (J.mode == M_LN) {
                float4 g0 = *(const float4*)&J.lng[col];
                float4 g1 = *(const float4*)&J.lng[col + 4];
                float4 o0 = *(const float4*)&J.lnb[col];
                float4 o1 = *(const float4*)&J.lnb[col + 4];
                v[0] = (v[0] - mean) * rstd * g0.x + o0.x;
                v[1] = (v[1] - mean) * rstd * g0.y + o0.y;
                v[2] = (v[2] - mean) * rstd * g0.z + o0.z;
                v[3] = (v[3] - mean) * rstd * g0.w + o0.w;
                v[4] = (v[4] - mean) * rstd * g1.x + o1.x;
                v[5] = (v[5] - mean) * rstd * g1.y + o1.y;
                v[6] = (v[6] - mean) * rstd * g1.z + o1.z;
                v[7] = (v[7] - mean) * rstd * g1.w + o1.w;
            }
            if (J.outf) {
                *(float4*)&J.outf[(size_t)m * J.ostride + J.ooff + col]     = *(float4*)&v[0];
                *(float4*)&J.outf[(size_t)m * J.ostride + J.ooff + col + 4] = *(float4*)&v[4];
            } else {
                *(uint4*)(J.o + swz(m, q * 4 + cq)) = pack8(v);
            }
        }
    }
}

// ---------------- prop body: 64 nodes/block, 2 nodes/warp, 16-lane rows ----
__device__ void prop_body(const PJob& P, int blk) {
    const int lane = threadIdx.x & 31, wid = threadIdx.x >> 5;
    const int half = lane >> 4, ch = lane & 15;
    for (int t = 0; t < 4; ++t) {
        const int i = blk * 64 + t * 16 + wid * 2 + half;
        const float di = g_dinv[i];
        float a[8], acc[8];
        rec8(P.n, swz(i, ch), a);
#pragma unroll
        for (int e = 0; e < 8; ++e) acc[e] = di * a[e];
        const int kc = g_kcnt[i];
        const int* kn = g_gn + i * KNBR;
        for (int k = 0; k < kc; ++k) {
            int j = kn[k];
            float dj = g_dinv[j];
            rec8(P.n, swz(j, ch), a);
#pragma unroll
            for (int e = 0; e < 8; ++e) acc[e] += dj * a[e];
        }
        rec8(P.r, swz(i, ch), a);                  // residual
        float v[8];
        float s = 0.f, ss = 0.f;
#pragma unroll
        for (int e = 0; e < 8; ++e) {
            v[e] = fmaxf(di * acc[e], 0.f) + a[e];
            s += v[e]; ss += v[e] * v[e];
        }
#pragma unroll
        for (int off = 1; off < 16; off <<= 1) {
            s  += __shfl_xor_sync(0xffffffffu, s,  off);
            ss += __shfl_xor_sync(0xffffffffu, ss, off);
        }
        float mean = s * (1.0f / 128.0f);
        float rstd = rsqrtf(ss * (1.0f / 128.0f) - mean * mean + LN_EPS);
        float4 g0 = *(const float4*)&P.lng[ch * 8];
        float4 g1 = *(const float4*)&P.lng[ch * 8 + 4];
        float4 o0 = *(const float4*)&P.lnb[ch * 8];
        float4 o1 = *(const float4*)&P.lnb[ch * 8 + 4];
        v[0] = (v[0] - mean) * rstd * g0.x + o0.x;
        v[1] = (v[1] - mean) * rstd * g0.y + o0.y;
        v[2] = (v[2] - mean) * rstd * g0.z + o0.z;
        v[3] = (v[3] - mean) * rstd * g0.w + o0.w;
        v[4] = (v[4] - mean) * rstd * g1.x + o1.x;
        v[5] = (v[5] - mean) * rstd * g1.y + o1.y;
        v[6] = (v[6] - mean) * rstd * g1.z + o1.z;
        v[7] = (v[7] - mean) * rstd * g1.w + o1.w;
        if (P.outf) {
            *(float4*)&P.outf[(size_t)i * P.ostride + P.ooff + ch * 8]     = *(float4*)&v[0];
            *(float4*)&P.outf[(size_t)i * P.ostride + P.ooff + ch * 8 + 4] = *(float4*)&v[4];
        } else {
            *(uint4*)(P.o + swz(i, ch)) = pack8(v);
        }
    }
}

#define GB (N_NODES / MTILE)    // 128 gemm tiles
#define PB (N_NODES / 64)       // 128 prop blocks

// ---------------- named step kernels ----------------------------------------
__global__ __launch_bounds__(THREADS, 3) void k_g2(GJob g0, GJob g1) {
    extern __shared__ __align__(256) char smem_raw[];
    int b = blockIdx.x;
    if (b < GB) gemm_body(g0, b, smem_raw);
    else        gemm_body(g1, b - GB, smem_raw);
}
__global__ __launch_bounds__(THREADS, 3) void k_gp(GJob g, PJob p) {
    extern __shared__ __align__(256) char smem_raw[];
    int b = blockIdx.x;
    if (b < GB) gemm_body(g, b, smem_raw);
    else        prop_body(p, b - GB);
}
__global__ __launch_bounds__(THREADS, 3) void k_g1(GJob g) {
    extern __shared__ __align__(256) char smem_raw[];
    gemm_body(g, blockIdx.x, smem_raw);
}
__global__ __launch_bounds__(THREADS) void k_p(PJob p) {
    prop_body(p, blockIdx.x);
}

// ---------------- driver ----------------------------------------------------
extern "C" void kernel_launch(void* const* d_in, const int* in_sizes, int n_in,
                              void* d_out, int out_size) {
    const float* x   = (const float*)d_in[0];
    const int*   nei = (const int*)  d_in[1];
    const int*   nbc = (const int*)  d_in[2];
    const float* gW  = (const float*)d_in[3];
    const float* gb  = (const float*)d_in[4];
    const float* glg = (const float*)d_in[5];
    const float* glb = (const float*)d_in[6];
    const float* pW  = (const float*)d_in[7];
    const float* pb  = (const float*)d_in[8];
    const float* mW  = (const float*)d_in[9];
    const float* mb  = (const float*)d_in[10];
    const float* slg = (const float*)d_in[11];
    const float* slb = (const float*)d_in[12];
    float* out = (float*)d_out;

    unsigned char *xp, *p0, *p1, *p2, *p3;
    cudaGetSymbolAddress((void**)&xp, g_x);
    cudaGetSymbolAddress((void**)&p0, g_p0);
    cudaGetSymbolAddress((void**)&p1, g_p1);
    cudaGetSymbolAddress((void**)&p2, g_p2);
    cudaGetSymbolAddress((void**)&p3, g_p3);

    cudaFuncSetAttribute(k_g2, cudaFuncAttributeMaxDynamicSharedMemorySize, SMEM_TOTAL);
    cudaFuncSetAttribute(k_gp, cudaFuncAttributeMaxDynamicSharedMemorySize, SMEM_TOTAL);
    cudaFuncSetAttribute(k_g1, cudaFuncAttributeMaxDynamicSharedMemorySize, SMEM_TOTAL);

    // G jobs (GCN): PLAIN -> p0 plane
    GJob G0 = { xp, nullptr, nullptr, gb,         nullptr, nullptr,
                nullptr, p0, 0, 1, M_PLAIN, D, 0 };
    GJob G1 = { p1, nullptr, nullptr, gb + D,     nullptr, nullptr,
                nullptr, p0, 1, 1, M_PLAIN, D, 0 };
    GJob G2 = { p1, nullptr, nullptr, gb + 2 * D, nullptr, nullptr,
                nullptr, p0, 2, 1, M_PLAIN, D, 0 };
    // S jobs (SAGE, pool fused as chunk 1)
    GJob S0 = { xp, nullptr, nullptr, pb,         nullptr, nullptr,
                nullptr, p2, 3, 1, M_RELU, D, 0 };
    GJob S1 = { xp, p2, nullptr, mb,              nullptr, nullptr,
                nullptr, p3, 4, 2, M_RELU, D, 0 };
    GJob S2 = { p3, p3, p3, mb + D,               slg, slb,
                nullptr, p2, 6, 2, M_LN, D, 0 };
    GJob S3 = { p2, p2, p2, mb + 2 * D,           slg + D, slb + D,
                out, nullptr, 8, 2, M_LN, 2 * D, D };
    // P jobs
    PJob P0 = { p0, p0, glg,         glb,         nullptr, p1, D, 0 };
    PJob P1 = { p0, p1, glg + D,     glb + D,     nullptr, p1, D, 0 };
    PJob P2 = { p0, p1, glg + 2 * D, glb + 2 * D, out, nullptr, 2 * D, 0 };

    prep_all_kernel<<<106, 256>>>(nei, nbc, gW, pW, mW, x);

    k_g2<<<2 * GB, THREADS, SMEM_TOTAL>>>(G0, S0);       // step1: G0 | S0
    k_gp<<<GB + PB, THREADS, SMEM_TOTAL>>>(S1, P0);      // step2: S1 | P0
    k_g2<<<2 * GB, THREADS, SMEM_TOTAL>>>(G1, S2);       // step3: G1 | S2
    k_gp<<<GB + PB, THREADS, SMEM_TOTAL>>>(S3, P1);      // step4: S3 | P1
    k_g1<<<GB, THREADS, SMEM_TOTAL>>>(G2);               // step5: G2
    k_p<<<PB, THREADS>>>(P2);                            // step6: P2
}

// round 16
// speedup vs baseline: 1.6825x; 1.0625x over previous
#include <cuda_runtime.h>
#include <cuda_fp16.h>
#include <cstdint>

#define N_NODES 8192
#define D 128
#define KNBR 8
#define LN_EPS 1e-5f

#define M_PLAIN 0
#define M_RELU  1
#define M_LN    2

#define MTILE 32
#define THREADS 256
// SMEM (bytes): A[32x128 fp16]=8K @0, W[128x128 fp16]=32K @8192
#define OFF_W 8192
#define SMEM_TOTAL 40960
#define WPLANE 32768           // one W chunk [128 n][128 k] fp16
#define ROWB 256               // bytes per activation row (128 fp16)

// ---------------- device globals (no allocation allowed) -------------------
// activation planes: fp16, swizzled rows (chunk ch at ((ch^(r&7))<<4))
__device__ __align__(16) unsigned char g_x[N_NODES * ROWB];
__device__ __align__(16) unsigned char g_p0[N_NODES * ROWB];
__device__ __align__(16) unsigned char g_p1[N_NODES * ROWB];
__device__ __align__(16) unsigned char g_p2[N_NODES * ROWB];
__device__ __align__(16) unsigned char g_p3[N_NODES * ROWB];
__device__ __align__(16) unsigned char g_p4[N_NODES * ROWB];
__device__ float g_dinv[N_NODES];
__device__ int   g_kcnt[N_NODES];
__device__ __align__(16) int g_gn[N_NODES * KNBR];      // gcn kept list, pad=i
__device__ __align__(16) int g_pooln[N_NODES * KNBR];   // pool list, pad=first
__device__ float g_pmul[N_NODES];                       // 0 if leaf else 1
// pre-converted, pre-swizzled weights: 10 chunks of [128 n][128 k] fp16
__device__ __align__(16) unsigned char g_w[10 * WPLANE];

// ---------------- job descriptors -------------------------------------------
struct GJob {
    const unsigned char* a;           // A chunk-0 plane (bulk path)
    const unsigned char* p;           // pool source plane (chunk 1)
    const unsigned char* r;           // residual plane (LN epilogue)
    const float *bias, *lng, *lnb;
    float* outf;                      // fp32 out (or null)
    unsigned char* o;                 // fp16 plane out (if outf null)
    // fused GCN-prop staging for chunk 0 (sprop != 0):
    const unsigned char* sn;          // prop nxt plane (cross-block reads;
                                      // MUST NOT alias o within a launch)
    const unsigned char* sr;          // prop residual plane (own-row reads)
    const float *slng, *slnb;         // prop LN params
    unsigned char* so;                // plane to materialize h (residual later)
    int sprop;
    int wchunk, nchunks, mode, ostride, ooff;
};
struct PJob {
    const unsigned char* n;           // nxt plane
    const unsigned char* r;           // res plane
    const float *lng, *lnb;
    float* outf;
    unsigned char* o;
    int ostride, ooff;
};

// ---------------- helpers ---------------------------------------------------
__device__ __forceinline__ uint32_t smem_u32(const void* p) {
    uint32_t a;
    asm("{ .reg .u64 t; cvta.to.shared.u64 t, %1; cvt.u32.u64 %0, t; }"
        : "=r"(a) : "l"(p));
    return a;
}
__device__ __forceinline__ void ldsm4(uint32_t addr, uint32_t* r) {
    asm volatile("ldmatrix.sync.aligned.m8n8.x4.shared.b16 {%0,%1,%2,%3}, [%4];"
                 : "=r"(r[0]), "=r"(r[1]), "=r"(r[2]), "=r"(r[3]) : "r"(addr));
}
__device__ __forceinline__ void mma_fp16(float* d, const uint32_t* a,
                                         uint32_t b0, uint32_t b1) {
    asm volatile(
        "mma.sync.aligned.m16n8k16.row.col.f32.f16.f16.f32 "
        "{%0,%1,%2,%3}, {%4,%5,%6,%7}, {%8,%9}, {%0,%1,%2,%3};"
        : "+f"(d[0]), "+f"(d[1]), "+f"(d[2]), "+f"(d[3])
        : "r"(a[0]), "r"(a[1]), "r"(a[2]), "r"(a[3]), "r"(b0), "r"(b1));
}
__device__ __forceinline__ void bulk_g2s(uint32_t dst, const void* src,
                                         uint32_t bytes, uint32_t mbar) {
    asm volatile(
        "cp.async.bulk.shared::cluster.global.mbarrier::complete_tx::bytes "
        "[%0], [%1], %2, [%3];"
        :: "r"(dst), "l"(src), "r"(bytes), "r"(mbar) : "memory");
}
__device__ __forceinline__ void mbar_init(uint32_t a, uint32_t cnt) {
    asm volatile("mbarrier.init.shared.b64 [%0], %1;" :: "r"(a), "r"(cnt) : "memory");
}
__device__ __forceinline__ void mbar_expect_tx(uint32_t a, uint32_t tx) {
    asm volatile("mbarrier.arrive.expect_tx.shared.b64 _, [%0], %1;"
                 :: "r"(a), "r"(tx) : "memory");
}
__device__ __forceinline__ void mbar_wait(uint32_t a, uint32_t parity) {
    asm volatile(
        "{\n\t.reg .pred P;\n\t"
        "WL_%=:\n\t"
        "mbarrier.try_wait.parity.acquire.cta.shared::cta.b64 P, [%0], %1, 0x989680;\n\t"
        "@P bra.uni WD_%=;\n\t"
        "bra.uni WL_%=;\n\t"
        "WD_%=:\n\t}"
        :: "r"(a), "r"(parity) : "memory");
}
static __device__ __forceinline__ uint32_t h2u(__half2 v) {
    return *reinterpret_cast<uint32_t*>(&v);
}
__device__ __forceinline__ uint4 pack8(const float* f) {
    uint4 o;
    o.x = h2u(__floats2half2_rn(f[0], f[1]));
    o.y = h2u(__floats2half2_rn(f[2], f[3]));
    o.z = h2u(__floats2half2_rn(f[4], f[5]));
    o.w = h2u(__floats2half2_rn(f[6], f[7]));
    return o;
}
__device__ __forceinline__ void rec8(const unsigned char* p, uint32_t off,
                                     float* v) {
    uint4 h = *(const uint4*)(p + off);
    float2 t;
    t = __half22float2(*(const __half2*)&h.x); v[0] = t.x; v[1] = t.y;
    t = __half22float2(*(const __half2*)&h.y); v[2] = t.x; v[3] = t.y;
    t = __half22float2(*(const __half2*)&h.z); v[4] = t.x; v[5] = t.y;
    t = __half22float2(*(const __half2*)&h.w); v[6] = t.x; v[7] = t.y;
}
__device__ __forceinline__ uint32_t swz(int r, int ch) {
    return (uint32_t)r * ROWB + ((uint32_t)(ch ^ (r & 7)) << 4);
}
__device__ __forceinline__ uint32_t hmax2u(uint32_t a, uint32_t b) {
    __half2 r = __hmax2(*reinterpret_cast<__half2*>(&a),
                        *reinterpret_cast<__half2*>(&b));
    return h2u(r);
}

// ---------------- prep: W cvt (0-9), graph (10-41), x cvt (42-105) ---------
__global__ void prep_all_kernel(const int* __restrict__ neigh,
                                const int* __restrict__ nbrc,
                                const float* __restrict__ gW,
                                const float* __restrict__ pW,
                                const float* __restrict__ mW,
                                const float* __restrict__ x) {
    int c = blockIdx.x, tid = threadIdx.x;
    if (c >= 42) {                       // x -> fp16 swizzled plane
        int base = (c - 42) * 128;
#pragma unroll
        for (int it = 0; it < 8; ++it) {
            int idx = tid + it * 256;
            int r = base + (idx >> 4), ch = idx & 15;
            float f[8];
            float4 f0 = *(const float4*)&x[r * D + ch * 8];
            float4 f1 = *(const float4*)&x[r * D + ch * 8 + 4];
            f[0]=f0.x; f[1]=f0.y; f[2]=f0.z; f[3]=f0.w;
            f[4]=f1.x; f[5]=f1.y; f[6]=f1.z; f[7]=f1.w;
            *(uint4*)(g_x + swz(r, ch)) = pack8(f);
        }
        return;
    }
    if (c >= 10) {                       // graph tables
        int i = (c - 10) * 256 + tid;
        int cnt = nbrc[i];
        cnt = cnt > KNBR ? KNBR : (cnt < 0 ? 0 : cnt);
        int first = cnt > 0 ? neigh[i * KNBR] : 0;
#pragma unroll
        for (int k = 0; k < KNBR; ++k)
            g_pooln[i * KNBR + k] = k < cnt ? neigh[i * KNBR + k] : first;
        g_pmul[i] = cnt > 0 ? 1.f : 0.f;
        int kept[KNBR];
        int kc = 0;
        for (int k = 0; k < cnt; ++k) {
            int nb = neigh[i * KNBR + k];
            if (nb == i) continue;
            bool dup = false;
            for (int t = 0; t < kc; ++t) if (kept[t] == nb) dup = true;
            if (!dup) kept[kc++] = nb;
        }
#pragma unroll
        for (int k = 0; k < KNBR; ++k)
            g_gn[i * KNBR + k] = k < kc ? kept[k] : i;
        g_kcnt[i] = kc;
        g_dinv[i] = rsqrtf((float)(kc + 1));
        return;
    }
    // W chunks
    const float* src;
    int stride, coloff;
    if (c < 3)       { src = gW + c * 16384; stride = 128; coloff = 0; }
    else if (c == 3) { src = pW;             stride = 128; coloff = 0; }
    else { int l = (c - 4) >> 1, h = (c - 4) & 1;
           src = mW + l * 32768; stride = 256; coloff = h * 128; }
    unsigned char* w = g_w + c * WPLANE;
    for (int i = tid; i < 2048; i += 256) {
        int n = i >> 4, ch = i & 15;
        float f[8];
#pragma unroll
        for (int e = 0; e < 8; ++e) f[e] = src[n * stride + coloff + ch * 8 + e];
        *(uint4*)(w + swz(n, ch)) = pack8(f);
    }
}

// ---------------- GEMM body: out = [A | pool(psrc)] @ W^T + b --------------
// single-pass fp16, fp32 accum. 8 warps, warp tile 16x32 (MTILE=32).
// chunk-0 staging: bulk A copy OR fused GCN prop (sprop).
__device__ void gemm_body(const GJob& J, int bid, char* smem_raw) {
    __shared__ __align__(8) uint64_t s_mbar;
    const uint32_t sbase = smem_u32(smem_raw);
    const uint32_t mbar = smem_u32(&s_mbar);
    const int tid = threadIdx.x, wid = tid >> 5, lane = tid & 31;
    const int wm = wid & 1, wn = wid >> 1;
    const int m0 = bid * MTILE;

    if (tid == 0) mbar_init(mbar, 1);
    __syncthreads();

    float acc[4][4];
#pragma unroll
    for (int j = 0; j < 4; ++j)
#pragma unroll
        for (int r = 0; r < 4; ++r) acc[j][r] = 0.f;

    const int lrow = lane & 15, lhalf = lane >> 4;
    const int rowA  = wm * 16 + lrow;
    const int rowB0 = wn * 32 + lrow, rowB1 = rowB0 + 16;

    for (int c = 0; c < J.nchunks; ++c) {
        if (c) __syncthreads();
        if (tid == 0) {
            uint32_t tx = WPLANE + ((c == 0 && !J.sprop) ? 8192u : 0u);
            mbar_expect_tx(mbar, tx);
            bulk_g2s(sbase + OFF_W, g_w + (J.wchunk + c) * WPLANE, WPLANE, mbar);
            if (c == 0 && !J.sprop)
                bulk_g2s(sbase, J.a + (size_t)m0 * ROWB, 8192, mbar);
        }
        if (c == 0 && J.sprop) {
            // fused GCN prop staging: h = LN(relu(di*sum dj*nxt[j]) + res)
            const int half = lane >> 4, chh = lane & 15;
#pragma unroll
            for (int t = 0; t < 2; ++t) {
                const int node = m0 + t * 16 + wid * 2 + half;
                const float di = g_dinv[node];
                float a8[8], ac[8];
                rec8(J.sn, swz(node, chh), a8);
#pragma unroll
                for (int e = 0; e < 8; ++e) ac[e] = di * a8[e];
                const int kc = g_kcnt[node];
                const int* kn = g_gn + node * KNBR;
                for (int k = 0; k < kc; ++k) {
                    int j = kn[k];
                    float dj = g_dinv[j];
                    rec8(J.sn, swz(j, chh), a8);
#pragma unroll
                    for (int e = 0; e < 8; ++e) ac[e] += dj * a8[e];
                }
                rec8(J.sr, swz(node, chh), a8);        // residual (own row)
                float v[8];
                float s = 0.f, ss = 0.f;
#pragma unroll
                for (int e = 0; e < 8; ++e) {
                    v[e] = fmaxf(di * ac[e], 0.f) + a8[e];
                    s += v[e]; ss += v[e] * v[e];
                }
#pragma unroll
                for (int off = 1; off < 16; off <<= 1) {
                    s  += __shfl_xor_sync(0xffffffffu, s,  off);
                    ss += __shfl_xor_sync(0xffffffffu, ss, off);
                }
                float mean = s * (1.0f / 128.0f);
                float rstd = rsqrtf(ss * (1.0f / 128.0f) - mean * mean + LN_EPS);
                float4 g0 = *(const float4*)&J.slng[chh * 8];
                float4 g1 = *(const float4*)&J.slng[chh * 8 + 4];
                float4 o0 = *(const float4*)&J.slnb[chh * 8];
                float4 o1 = *(const float4*)&J.slnb[chh * 8 + 4];
                v[0] = (v[0] - mean) * rstd * g0.x + o0.x;
                v[1] = (v[1] - mean) * rstd * g0.y + o0.y;
                v[2] = (v[2] - mean) * rstd * g0.z + o0.z;
                v[3] = (v[3] - mean) * rstd * g0.w + o0.w;
                v[4] = (v[4] - mean) * rstd * g1.x + o1.x;
                v[5] = (v[5] - mean) * rstd * g1.y + o1.y;
                v[6] = (v[6] - mean) * rstd * g1.z + o1.z;
                v[7] = (v[7] - mean) * rstd * g1.w + o1.w;
                uint4 pk = pack8(v);
                *(uint4*)(smem_raw + swz(node - m0, chh)) = pk;   // A tile
                *(uint4*)(J.so + swz(node, chh)) = pk;            // h plane
            }
        }
        if (c == 1) {
            // fused max-pool gather into A smem (fp16, swizzled, hmax2)
            for (int i = tid; i < 512; i += THREADS) {
                int r = i >> 4, ch = i & 15;
                int node = m0 + r;
                const int4* nl = (const int4*)(g_pooln + node * KNBR);
                int4 na = nl[0], nb = nl[1];
                int idx[8] = { na.x, na.y, na.z, na.w, nb.x, nb.y, nb.z, nb.w };
                uint4 mv = *(const uint4*)(J.p + swz(idx[0], ch));
#pragma unroll
                for (int t = 1; t < 8; ++t) {
                    uint4 tv = *(const uint4*)(J.p + swz(idx[t], ch));
                    mv.x = hmax2u(mv.x, tv.x);
                    mv.y = hmax2u(mv.y, tv.y);
                    mv.z = hmax2u(mv.z, tv.z);
                    mv.w = hmax2u(mv.w, tv.w);
                }
                if (g_pmul[node] == 0.f) mv = make_uint4(0, 0, 0, 0);
                *(uint4*)(smem_raw + swz(r, ch)) = mv;
            }
        }
        __syncthreads();
        mbar_wait(mbar, c & 1);

#pragma unroll
        for (int ks = 0; ks < 8; ++ks) {
            const int ch = ks * 2 + lhalf;
            uint32_t a[4], b0[4], b1[4];
            ldsm4(sbase + swz(rowA, ch), a);
            ldsm4(sbase + OFF_W + swz(rowB0, ch), b0);
            ldsm4(sbase + OFF_W + swz(rowB1, ch), b1);
            mma_fp16(acc[0], a, b0[0], b0[2]);
            mma_fp16(acc[1], a, b0[1], b0[3]);
            mma_fp16(acc[2], a, b1[0], b1[2]);
            mma_fp16(acc[3], a, b1[1], b1[3]);
        }
    }

    // ---- epilogue: fragments -> sC fp32 (bias [+relu]) -> per-row finish --
    const int frow = lane >> 2, fcol = 2 * (lane & 3);
    float* sC = (float*)smem_raw;                 // [32][132]
    __syncthreads();
#pragma unroll
    for (int j = 0; j < 4; ++j) {
        int ncol = wn * 32 + j * 8 + fcol;
        float2 bj = *(const float2*)&J.bias[ncol];
        int r = wm * 16 + frow;
        float v0 = acc[j][0] + bj.x, v1 = acc[j][1] + bj.y;
        float v2 = acc[j][2] + bj.x, v3 = acc[j][3] + bj.y;
        if (J.mode != M_PLAIN) {
            v0 = fmaxf(v0, 0.f); v1 = fmaxf(v1, 0.f);
            v2 = fmaxf(v2, 0.f); v3 = fmaxf(v3, 0.f);
        }
        sC[r * 132 + ncol]           = v0;
        sC[r * 132 + ncol + 1]       = v1;
        sC[(r + 8) * 132 + ncol]     = v2;
        sC[(r + 8) * 132 + ncol + 1] = v3;
    }
    __syncthreads();

    {
        const int row = tid >> 3, q = tid & 7;     // 8 threads/row, 32 rows
        const int m = m0 + row;
        float mean = 0.f, rstd = 1.f;
        if (J.mode == M_LN) {
            float s = 0.f, ss = 0.f;
#pragma unroll
            for (int cc = 0; cc < 2; ++cc) {
                int ch = q * 2 + cc;
                float r8[8];
                rec8(J.r, swz(m, ch), r8);
                float* cp = &sC[row * 132 + ch * 8];
                float4 a0 = *(float4*)cp, a1 = *(float4*)(cp + 4);
                a0.x += r8[0]; a0.y += r8[1]; a0.z += r8[2]; a0.w += r8[3];
                a1.x += r8[4]; a1.y += r8[5]; a1.z += r8[6]; a1.w += r8[7];
                s  += a0.x + a0.y + a0.z + a0.w + a1.x + a1.y + a1.z + a1.w;
                ss += a0.x * a0.x + a0.y * a0.y + a0.z * a0.z + a0.w * a0.w +
                      a1.x * a1.x + a1.y * a1.y + a1.z * a1.z + a1.w * a1.w;
                *(float4*)cp = a0;
                *(float4*)(cp + 4) = a1;
            }
#pragma unroll
            for (int off = 1; off < 8; off <<= 1) {
                s  += __shfl_xor_sync(0xffffffffu, s,  off);
                ss += __shfl_xor_sync(0xffffffffu, ss, off);
            }
            mean = s * (1.0f / 128.0f);
            rstd = rsqrtf(ss * (1.0f / 128.0f) - mean * mean + LN_EPS);
        }
#pragma unroll
        for (int cc = 0; cc < 2; ++cc) {
            int ch = q * 2 + cc;
            int col = ch * 8;
            float* cp = &sC[row * 132 + col];
            float v[8];
            *(float4*)&v[0] = *(float4*)cp;
            *(float4*)&v[4] = *(float4*)(cp + 4);
            if (J.mode == M_LN) {
                float4 g0 = *(const float4*)&J.lng[col];
                float4 g1 = *(const float4*)&J.lng[col + 4];
                float4 o0 = *(const float4*)&J.lnb[col];
                float4 o1 = *(const float4*)&J.lnb[col + 4];
                v[0] = (v[0] - mean) * rstd * g0.x + o0.x;
                v[1] = (v[1] - mean) * rstd * g0.y + o0.y;
                v[2] = (v[2] - mean) * rstd * g0.z + o0.z;
                v[3] = (v[3] - mean) * rstd * g0.w + o0.w;
                v[4] = (v[4] - mean) * rstd * g1.x + o1.x;
                v[5] = (v[5] - mean) * rstd * g1.y + o1.y;
                v[6] = (v[6] - mean) * rstd * g1.z + o1.z;
                v[7] = (v[7] - mean) * rstd * g1.w + o1.w;
            }
            if (J.outf) {
                *(float4*)&J.outf[(size_t)m * J.ostride + J.ooff + col]     = *(float4*)&v[0];
                *(float4*)&J.outf[(size_t)m * J.ostride + J.ooff + col + 4] = *(float4*)&v[4];
            } else {
                *(uint4*)(J.o + swz(m, ch)) = pack8(v);
            }
        }
    }
}

// ---------------- prop body: 64 nodes/block, 2 nodes/warp, 16-lane rows ----
__device__ void prop_body(const PJob& P, int blk) {
    const int lane = threadIdx.x & 31, wid = threadIdx.x >> 5;
    const int half = lane >> 4, ch = lane & 15;
    for (int t = 0; t < 4; ++t) {
        const int i = blk * 64 + t * 16 + wid * 2 + half;
        const float di = g_dinv[i];
        float a[8], acc[8];
        rec8(P.n, swz(i, ch), a);
#pragma unroll
        for (int e = 0; e < 8; ++e) acc[e] = di * a[e];
        const int kc = g_kcnt[i];
        const int* kn = g_gn + i * KNBR;
        for (int k = 0; k < kc; ++k) {
            int j = kn[k];
            float dj = g_dinv[j];
            rec8(P.n, swz(j, ch), a);
#pragma unroll
            for (int e = 0; e < 8; ++e) acc[e] += dj * a[e];
        }
        rec8(P.r, swz(i, ch), a);                  // residual
        float v[8];
        float s = 0.f, ss = 0.f;
#pragma unroll
        for (int e = 0; e < 8; ++e) {
            v[e] = fmaxf(di * acc[e], 0.f) + a[e];
            s += v[e]; ss += v[e] * v[e];
        }
#pragma unroll
        for (int off = 1; off < 16; off <<= 1) {
            s  += __shfl_xor_sync(0xffffffffu, s,  off);
            ss += __shfl_xor_sync(0xffffffffu, ss, off);
        }
        float mean = s * (1.0f / 128.0f);
        float rstd = rsqrtf(ss * (1.0f / 128.0f) - mean * mean + LN_EPS);
        float4 g0 = *(const float4*)&P.lng[ch * 8];
        float4 g1 = *(const float4*)&P.lng[ch * 8 + 4];
        float4 o0 = *(const float4*)&P.lnb[ch * 8];
        float4 o1 = *(const float4*)&P.lnb[ch * 8 + 4];
        v[0] = (v[0] - mean) * rstd * g0.x + o0.x;
        v[1] = (v[1] - mean) * rstd * g0.y + o0.y;
        v[2] = (v[2] - mean) * rstd * g0.z + o0.z;
        v[3] = (v[3] - mean) * rstd * g0.w + o0.w;
        v[4] = (v[4] - mean) * rstd * g1.x + o1.x;
        v[5] = (v[5] - mean) * rstd * g1.y + o1.y;
        v[6] = (v[6] - mean) * rstd * g1.z + o1.z;
        v[7] = (v[7] - mean) * rstd * g1.w + o1.w;
        if (P.outf) {
            *(float4*)&P.outf[(size_t)i * P.ostride + P.ooff + ch * 8]     = *(float4*)&v[0];
            *(float4*)&P.outf[(size_t)i * P.ostride + P.ooff + ch * 8 + 4] = *(float4*)&v[4];
        } else {
            *(uint4*)(P.o + swz(i, ch)) = pack8(v);
        }
    }
}

#define GB (N_NODES / MTILE)    // 256 gemm tiles
#define PB (N_NODES / 64)       // 128 prop blocks

// ---------------- named step kernels ----------------------------------------
__global__ __launch_bounds__(THREADS, 4) void k_g2(GJob g0, GJob g1) {
    extern __shared__ __align__(256) char smem_raw[];
    int b = blockIdx.x;
    if (b < GB) gemm_body(g0, b, smem_raw);
    else        gemm_body(g1, b - GB, smem_raw);
}
__global__ __launch_bounds__(THREADS, 4) void k_gp(GJob g, PJob p) {
    extern __shared__ __align__(256) char smem_raw[];
    int b = blockIdx.x;
    if (b < GB) gemm_body(g, b, smem_raw);
    else        prop_body(p, b - GB);
}

// ---------------- driver ----------------------------------------------------
extern "C" void kernel_launch(void* const* d_in, const int* in_sizes, int n_in,
                              void* d_out, int out_size) {
    const float* x   = (const float*)d_in[0];
    const int*   nei = (const int*)  d_in[1];
    const int*   nbc = (const int*)  d_in[2];
    const float* gW  = (const float*)d_in[3];
    const float* gb  = (const float*)d_in[4];
    const float* glg = (const float*)d_in[5];
    const float* glb = (const float*)d_in[6];
    const float* pW  = (const float*)d_in[7];
    const float* pb  = (const float*)d_in[8];
    const float* mW  = (const float*)d_in[9];
    const float* mb  = (const float*)d_in[10];
    const float* slg = (const float*)d_in[11];
    const float* slb = (const float*)d_in[12];
    float* out = (float*)d_out;

    unsigned char *xp, *p0, *p1, *p2, *p3, *p4;
    cudaGetSymbolAddress((void**)&xp, g_x);
    cudaGetSymbolAddress((void**)&p0, g_p0);
    cudaGetSymbolAddress((void**)&p1, g_p1);
    cudaGetSymbolAddress((void**)&p2, g_p2);
    cudaGetSymbolAddress((void**)&p3, g_p3);
    cudaGetSymbolAddress((void**)&p4, g_p4);

    cudaFuncSetAttribute(k_g2, cudaFuncAttributeMaxDynamicSharedMemorySize, SMEM_TOTAL);
    cudaFuncSetAttribute(k_gp, cudaFuncAttributeMaxDynamicSharedMemorySize, SMEM_TOTAL);

    // --- GCN jobs (plane schedule avoids cross-block read/write aliasing) ---
    // step1: nxt0 = x@W0+b0 -> p0
    GJob G0  = { xp, nullptr, nullptr, gb, nullptr, nullptr, nullptr, p0,
                 nullptr, nullptr, nullptr, nullptr, nullptr, 0,
                 0, 1, M_PLAIN, D, 0 };
    // step2: stage h1 = LN(relu(prop(p0)) + p0) -> SMEM + p1; nxt1 = h1@W1 -> p4
    GJob G1p = { nullptr, nullptr, nullptr, gb + D, nullptr, nullptr, nullptr, p4,
                 p0, p0, glg, glb, p1, 1,
                 1, 1, M_PLAIN, D, 0 };
    // step3: stage h2 = LN(relu(prop(p4)) + p1) -> SMEM + p1; nxt2 = h2@W2 -> p0
    GJob G2p = { nullptr, nullptr, nullptr, gb + 2 * D, nullptr, nullptr, nullptr, p0,
                 p4, p1, glg + D, glb + D, p1, 1,
                 2, 1, M_PLAIN, D, 0 };
    // --- SAGE jobs (pool fused as chunk 1) ---
    GJob S0  = { xp, nullptr, nullptr, pb, nullptr, nullptr, nullptr, p2,
                 nullptr, nullptr, nullptr, nullptr, nullptr, 0,
                 3, 1, M_RELU, D, 0 };
    GJob S1  = { xp, p2, nullptr, mb, nullptr, nullptr, nullptr, p3,
                 nullptr, nullptr, nullptr, nullptr, nullptr, 0,
                 4, 2, M_RELU, D, 0 };
    GJob S2  = { p3, p3, p3, mb + D, slg, slb, nullptr, p2,
                 nullptr, nullptr, nullptr, nullptr, nullptr, 0,
                 6, 2, M_LN, D, 0 };
    GJob S3  = { p2, p2, p2, mb + 2 * D, slg + D, slb + D, out, nullptr,
                 nullptr, nullptr, nullptr, nullptr, nullptr, 0,
                 8, 2, M_LN, 2 * D, D };
    // step4: final GCN prop: out[:,0:128] = LN(relu(prop(p0)) + p1)
    PJob P2  = { p0, p1, glg + 2 * D, glb + 2 * D, out, nullptr, 2 * D, 0 };

    prep_all_kernel<<<106, 256>>>(nei, nbc, gW, pW, mW, x);

    k_g2<<<2 * GB, THREADS, SMEM_TOTAL>>>(G0, S0);        // step1: G0  | S0
    k_g2<<<2 * GB, THREADS, SMEM_TOTAL>>>(G1p, S1);       // step2: G1p | S1
    k_g2<<<2 * GB, THREADS, SMEM_TOTAL>>>(G2p, S2);       // step3: G2p | S2
    k_gp<<<GB + PB, THREADS, SMEM_TOTAL>>>(S3, P2);       // step4: S3  | P2
}

// round 17
// speedup vs baseline: 1.8552x; 1.1026x over previous
#include <cuda_runtime.h>
#include <cuda_fp16.h>
#include <cstdint>

#define N_NODES 8192
#define D 128
#define KNBR 8
#define LN_EPS 1e-5f

#define M_PLAIN 0
#define M_RELU  1
#define M_LN    2

#define MTILE 32
#define THREADS 256
// SMEM (bytes): A[32x128 fp16]=8K @0, W[128x128 fp16]=32K @8192
#define OFF_W 8192
#define SMEM_TOTAL 40960
#define WPLANE 32768           // one W chunk [128 n][128 k] fp16
#define ROWB 256               // bytes per activation row (128 fp16)

// ---------------- device globals (no allocation allowed) -------------------
// activation planes: fp16, swizzled rows (chunk ch at ((ch^(r&7))<<4))
__device__ __align__(16) unsigned char g_x[N_NODES * ROWB];
__device__ __align__(16) unsigned char g_p0[N_NODES * ROWB];
__device__ __align__(16) unsigned char g_p1[N_NODES * ROWB];
__device__ __align__(16) unsigned char g_p2[N_NODES * ROWB];
__device__ __align__(16) unsigned char g_p3[N_NODES * ROWB];
__device__ __align__(16) unsigned char g_p4[N_NODES * ROWB];
__device__ float g_dinv[N_NODES];
__device__ int   g_kcnt[N_NODES];
__device__ __align__(16) int   g_gn[N_NODES * KNBR];    // gcn kept list, pad=i
__device__ __align__(16) float g_gwt[N_NODES * KNBR];   // dinv[j] or 0 (pad)
__device__ __align__(16) int   g_pooln[N_NODES * KNBR]; // pool list, pad=first
__device__ float g_pmul[N_NODES];                       // 0 if leaf else 1
// pre-converted, pre-swizzled weights: 10 chunks of [128 n][128 k] fp16
__device__ __align__(16) unsigned char g_w[10 * WPLANE];

// ---------------- job descriptors -------------------------------------------
struct GJob {
    const unsigned char* a;           // A chunk-0 plane (bulk path)
    const unsigned char* p;           // pool source plane (chunk 1)
    const unsigned char* r;           // residual plane (LN epilogue)
    const float *bias, *lng, *lnb;
    float* outf;                      // fp32 out (or null)
    unsigned char* o;                 // fp16 plane out (if outf null)
    // fused GCN-prop staging for chunk 0 (sprop != 0):
    const unsigned char* sn;          // prop nxt plane (cross-block reads;
                                      // MUST NOT alias o within a launch)
    const unsigned char* sr;          // prop residual plane (own-row reads)
    const float *slng, *slnb;         // prop LN params
    unsigned char* so;                // plane to materialize h (residual later)
    int sprop;
    int wchunk, nchunks, mode, ostride, ooff;
};
struct PJob {
    const unsigned char* n;           // nxt plane
    const unsigned char* r;           // res plane
    const float *lng, *lnb;
    float* outf;
    unsigned char* o;
    int ostride, ooff;
};

// ---------------- helpers ---------------------------------------------------
__device__ __forceinline__ uint32_t smem_u32(const void* p) {
    uint32_t a;
    asm("{ .reg .u64 t; cvta.to.shared.u64 t, %1; cvt.u32.u64 %0, t; }"
        : "=r"(a) : "l"(p));
    return a;
}
__device__ __forceinline__ void ldsm4(uint32_t addr, uint32_t* r) {
    asm volatile("ldmatrix.sync.aligned.m8n8.x4.shared.b16 {%0,%1,%2,%3}, [%4];"
                 : "=r"(r[0]), "=r"(r[1]), "=r"(r[2]), "=r"(r[3]) : "r"(addr));
}
__device__ __forceinline__ void mma_fp16(float* d, const uint32_t* a,
                                         uint32_t b0, uint32_t b1) {
    asm volatile(
        "mma.sync.aligned.m16n8k16.row.col.f32.f16.f16.f32 "
        "{%0,%1,%2,%3}, {%4,%5,%6,%7}, {%8,%9}, {%0,%1,%2,%3};"
        : "+f"(d[0]), "+f"(d[1]), "+f"(d[2]), "+f"(d[3])
        : "r"(a[0]), "r"(a[1]), "r"(a[2]), "r"(a[3]), "r"(b0), "r"(b1));
}
__device__ __forceinline__ void bulk_g2s(uint32_t dst, const void* src,
                                         uint32_t bytes, uint32_t mbar) {
    asm volatile(
        "cp.async.bulk.shared::cluster.global.mbarrier::complete_tx::bytes "
        "[%0], [%1], %2, [%3];"
        :: "r"(dst), "l"(src), "r"(bytes), "r"(mbar) : "memory");
}
__device__ __forceinline__ void mbar_init(uint32_t a, uint32_t cnt) {
    asm volatile("mbarrier.init.shared.b64 [%0], %1;" :: "r"(a), "r"(cnt) : "memory");
}
__device__ __forceinline__ void mbar_expect_tx(uint32_t a, uint32_t tx) {
    asm volatile("mbarrier.arrive.expect_tx.shared.b64 _, [%0], %1;"
                 :: "r"(a), "r"(tx) : "memory");
}
__device__ __forceinline__ void mbar_wait(uint32_t a, uint32_t parity) {
    asm volatile(
        "{\n\t.reg .pred P;\n\t"
        "WL_%=:\n\t"
        "mbarrier.try_wait.parity.acquire.cta.shared::cta.b64 P, [%0], %1, 0x989680;\n\t"
        "@P bra.uni WD_%=;\n\t"
        "bra.uni WL_%=;\n\t"
        "WD_%=:\n\t}"
        :: "r"(a), "r"(parity) : "memory");
}
static __device__ __forceinline__ uint32_t h2u(__half2 v) {
    return *reinterpret_cast<uint32_t*>(&v);
}
__device__ __forceinline__ uint4 pack8(const float* f) {
    uint4 o;
    o.x = h2u(__floats2half2_rn(f[0], f[1]));
    o.y = h2u(__floats2half2_rn(f[2], f[3]));
    o.z = h2u(__floats2half2_rn(f[4], f[5]));
    o.w = h2u(__floats2half2_rn(f[6], f[7]));
    return o;
}
__device__ __forceinline__ void rec8(const unsigned char* p, uint32_t off,
                                     float* v) {
    uint4 h = *(const uint4*)(p + off);
    float2 t;
    t = __half22float2(*(const __half2*)&h.x); v[0] = t.x; v[1] = t.y;
    t = __half22float2(*(const __half2*)&h.y); v[2] = t.x; v[3] = t.y;
    t = __half22float2(*(const __half2*)&h.z); v[4] = t.x; v[5] = t.y;
    t = __half22float2(*(const __half2*)&h.w); v[6] = t.x; v[7] = t.y;
}
__device__ __forceinline__ uint32_t swz(int r, int ch) {
    return (uint32_t)r * ROWB + ((uint32_t)(ch ^ (r & 7)) << 4);
}
__device__ __forceinline__ uint32_t hmax2u(uint32_t a, uint32_t b) {
    __half2 r = __hmax2(*reinterpret_cast<__half2*>(&a),
                        *reinterpret_cast<__half2*>(&b));
    return h2u(r);
}

// padded branch-free weighted gather: acc = di*self + sum_k w[k]*nxt[j_k]
__device__ __forceinline__ void prop_gather(const unsigned char* plane,
                                            int node, int chh, float di,
                                            float* ac) {
    const int4* nl4 = (const int4*)(g_gn + node * KNBR);
    const float4* wt = (const float4*)(g_gwt + node * KNBR);
    int4 na = nl4[0], nb = nl4[1];
    float4 w0 = wt[0], w1 = wt[1];
    float a8[8];
    rec8(plane, swz(node, chh), a8);
#pragma unroll
    for (int e = 0; e < 8; ++e) ac[e] = di * a8[e];
    int   idx[8] = { na.x, na.y, na.z, na.w, nb.x, nb.y, nb.z, nb.w };
    float ww[8]  = { w0.x, w0.y, w0.z, w0.w, w1.x, w1.y, w1.z, w1.w };
#pragma unroll
    for (int t = 0; t < 8; ++t) {
        float t8[8];
        rec8(plane, swz(idx[t], chh), t8);
#pragma unroll
        for (int e = 0; e < 8; ++e) ac[e] += ww[t] * t8[e];
    }
}

// ---------------- prep: W cvt (0-9), graph (10-41), x cvt (42-105) ---------
__global__ void prep_all_kernel(const int* __restrict__ neigh,
                                const int* __restrict__ nbrc,
                                const float* __restrict__ gW,
                                const float* __restrict__ pW,
                                const float* __restrict__ mW,
                                const float* __restrict__ x) {
    int c = blockIdx.x, tid = threadIdx.x;
    if (c >= 42) {                       // x -> fp16 swizzled plane
        int base = (c - 42) * 128;
#pragma unroll
        for (int it = 0; it < 8; ++it) {
            int idx = tid + it * 256;
            int r = base + (idx >> 4), ch = idx & 15;
            float f[8];
            float4 f0 = *(const float4*)&x[r * D + ch * 8];
            float4 f1 = *(const float4*)&x[r * D + ch * 8 + 4];
            f[0]=f0.x; f[1]=f0.y; f[2]=f0.z; f[3]=f0.w;
            f[4]=f1.x; f[5]=f1.y; f[6]=f1.z; f[7]=f1.w;
            *(uint4*)(g_x + swz(r, ch)) = pack8(f);
        }
        return;
    }
    if (c >= 10) {                       // graph tables
        int i = (c - 10) * 256 + tid;
        int cnt = nbrc[i];
        cnt = cnt > KNBR ? KNBR : (cnt < 0 ? 0 : cnt);
        int first = cnt > 0 ? neigh[i * KNBR] : 0;
#pragma unroll
        for (int k = 0; k < KNBR; ++k)
            g_pooln[i * KNBR + k] = k < cnt ? neigh[i * KNBR + k] : first;
        g_pmul[i] = cnt > 0 ? 1.f : 0.f;
        int kept[KNBR];
        int kc = 0;
        for (int k = 0; k < cnt; ++k) {
            int nb = neigh[i * KNBR + k];
            if (nb == i) continue;
            bool dup = false;
            for (int t = 0; t < kc; ++t) if (kept[t] == nb) dup = true;
            if (!dup) kept[kc++] = nb;
        }
#pragma unroll
        for (int k = 0; k < KNBR; ++k)
            g_gn[i * KNBR + k] = k < kc ? kept[k] : i;
        g_kcnt[i] = kc;
        g_dinv[i] = rsqrtf((float)(kc + 1));
        return;
    }
    // W chunks
    const float* src;
    int stride, coloff;
    if (c < 3)       { src = gW + c * 16384; stride = 128; coloff = 0; }
    else if (c == 3) { src = pW;             stride = 128; coloff = 0; }
    else { int l = (c - 4) >> 1, h = (c - 4) & 1;
           src = mW + l * 32768; stride = 256; coloff = h * 128; }
    unsigned char* w = g_w + c * WPLANE;
    for (int i = tid; i < 2048; i += 256) {
        int n = i >> 4, ch = i & 15;
        float f[8];
#pragma unroll
        for (int e = 0; e < 8; ++e) f[e] = src[n * stride + coloff + ch * 8 + e];
        *(uint4*)(w + swz(n, ch)) = pack8(f);
    }
}

// second prep pass: weight table needs completed g_dinv across all nodes
__global__ void prep2_kernel() {
    int i = blockIdx.x * 256 + threadIdx.x;
    int kc = g_kcnt[i];
#pragma unroll
    for (int k = 0; k < KNBR; ++k) {
        int j = g_gn[i * KNBR + k];
        g_gwt[i * KNBR + k] = (k < kc) ? g_dinv[j] : 0.f;
    }
}

// ---------------- GEMM body: out = [A | pool(psrc)] @ W^T + b --------------
// single-pass fp16, fp32 accum. 8 warps, warp tile 16x32 (MTILE=32).
// chunk-0 staging: bulk A copy OR fused GCN prop (sprop).
__device__ void gemm_body(const GJob& J, int bid, char* smem_raw) {
    __shared__ __align__(8) uint64_t s_mbar;
    const uint32_t sbase = smem_u32(smem_raw);
    const uint32_t mbar = smem_u32(&s_mbar);
    const int tid = threadIdx.x, wid = tid >> 5, lane = tid & 31;
    const int wm = wid & 1, wn = wid >> 1;
    const int m0 = bid * MTILE;

    if (tid == 0) mbar_init(mbar, 1);
    __syncthreads();

    float acc[4][4];
#pragma unroll
    for (int j = 0; j < 4; ++j)
#pragma unroll
        for (int r = 0; r < 4; ++r) acc[j][r] = 0.f;

    const int lrow = lane & 15, lhalf = lane >> 4;
    const int rowA  = wm * 16 + lrow;
    const int rowB0 = wn * 32 + lrow, rowB1 = rowB0 + 16;

    for (int c = 0; c < J.nchunks; ++c) {
        if (c) __syncthreads();
        if (tid == 0) {
            uint32_t tx = WPLANE + ((c == 0 && !J.sprop) ? 8192u : 0u);
            mbar_expect_tx(mbar, tx);
            bulk_g2s(sbase + OFF_W, g_w + (J.wchunk + c) * WPLANE, WPLANE, mbar);
            if (c == 0 && !J.sprop)
                bulk_g2s(sbase, J.a + (size_t)m0 * ROWB, 8192, mbar);
        }
        if (c == 0 && J.sprop) {
            // fused GCN prop staging: h = LN(relu(di*gather) + res)
            const int half = lane >> 4, chh = lane & 15;
#pragma unroll
            for (int t = 0; t < 2; ++t) {
                const int node = m0 + t * 16 + wid * 2 + half;
                const float di = g_dinv[node];
                float ac[8], a8[8];
                prop_gather(J.sn, node, chh, di, ac);
                rec8(J.sr, swz(node, chh), a8);        // residual (own row)
                float v[8];
                float s = 0.f, ss = 0.f;
#pragma unroll
                for (int e = 0; e < 8; ++e) {
                    v[e] = fmaxf(di * ac[e], 0.f) + a8[e];
                    s += v[e]; ss += v[e] * v[e];
                }
#pragma unroll
                for (int off = 1; off < 16; off <<= 1) {
                    s  += __shfl_xor_sync(0xffffffffu, s,  off);
                    ss += __shfl_xor_sync(0xffffffffu, ss, off);
                }
                float mean = s * (1.0f / 128.0f);
                float rstd = rsqrtf(ss * (1.0f / 128.0f) - mean * mean + LN_EPS);
                float4 g0 = *(const float4*)&J.slng[chh * 8];
                float4 g1 = *(const float4*)&J.slng[chh * 8 + 4];
                float4 o0 = *(const float4*)&J.slnb[chh * 8];
                float4 o1 = *(const float4*)&J.slnb[chh * 8 + 4];
                v[0] = (v[0] - mean) * rstd * g0.x + o0.x;
                v[1] = (v[1] - mean) * rstd * g0.y + o0.y;
                v[2] = (v[2] - mean) * rstd * g0.z + o0.z;
                v[3] = (v[3] - mean) * rstd * g0.w + o0.w;
                v[4] = (v[4] - mean) * rstd * g1.x + o1.x;
                v[5] = (v[5] - mean) * rstd * g1.y + o1.y;
                v[6] = (v[6] - mean) * rstd * g1.z + o1.z;
                v[7] = (v[7] - mean) * rstd * g1.w + o1.w;
                uint4 pk = pack8(v);
                *(uint4*)(smem_raw + swz(node - m0, chh)) = pk;   // A tile
                *(uint4*)(J.so + swz(node, chh)) = pk;            // h plane
            }
        }
        if (c == 1) {
            // fused max-pool gather into A smem (fp16, swizzled, hmax2)
            for (int i = tid; i < 512; i += THREADS) {
                int r = i >> 4, ch = i & 15;
                int node = m0 + r;
                const int4* nl = (const int4*)(g_pooln + node * KNBR);
                int4 na = nl[0], nb = nl[1];
                int idx[8] = { na.x, na.y, na.z, na.w, nb.x, nb.y, nb.z, nb.w };
                uint4 mv = *(const uint4*)(J.p + swz(idx[0], ch));
#pragma unroll
                for (int t = 1; t < 8; ++t) {
                    uint4 tv = *(const uint4*)(J.p + swz(idx[t], ch));
                    mv.x = hmax2u(mv.x, tv.x);
                    mv.y = hmax2u(mv.y, tv.y);
                    mv.z = hmax2u(mv.z, tv.z);
                    mv.w = hmax2u(mv.w, tv.w);
                }
                if (g_pmul[node] == 0.f) mv = make_uint4(0, 0, 0, 0);
                *(uint4*)(smem_raw + swz(r, ch)) = mv;
            }
        }
        __syncthreads();
        mbar_wait(mbar, c & 1);

#pragma unroll
        for (int ks = 0; ks < 8; ++ks) {
            const int ch = ks * 2 + lhalf;
            uint32_t a[4], b0[4], b1[4];
            ldsm4(sbase + swz(rowA, ch), a);
            ldsm4(sbase + OFF_W + swz(rowB0, ch), b0);
            ldsm4(sbase + OFF_W + swz(rowB1, ch), b1);
            mma_fp16(acc[0], a, b0[0], b0[2]);
            mma_fp16(acc[1], a, b0[1], b0[3]);
            mma_fp16(acc[2], a, b1[0], b1[2]);
            mma_fp16(acc[3], a, b1[1], b1[3]);
        }
    }

    // ---- epilogue: fragments -> sC fp32 (bias [+relu]) -> per-row finish --
    const int frow = lane >> 2, fcol = 2 * (lane & 3);
    float* sC = (float*)smem_raw;                 // [32][132]
    __syncthreads();
#pragma unroll
    for (int j = 0; j < 4; ++j) {
        int ncol = wn * 32 + j * 8 + fcol;
        float2 bj = *(const float2*)&J.bias[ncol];
        int r = wm * 16 + frow;
        float v0 = acc[j][0] + bj.x, v1 = acc[j][1] + bj.y;
        float v2 = acc[j][2] + bj.x, v3 = acc[j][3] + bj.y;
        if (J.mode != M_PLAIN) {
            v0 = fmaxf(v0, 0.f); v1 = fmaxf(v1, 0.f);
            v2 = fmaxf(v2, 0.f); v3 = fmaxf(v3, 0.f);
        }
        sC[r * 132 + ncol]           = v0;
        sC[r * 132 + ncol + 1]       = v1;
        sC[(r + 8) * 132 + ncol]     = v2;
        sC[(r + 8) * 132 + ncol + 1] = v3;
    }
    __syncthreads();

    {
        const int row = tid >> 3, q = tid & 7;     // 8 threads/row, 32 rows
        const int m = m0 + row;
        float mean = 0.f, rstd = 1.f;
        if (J.mode == M_LN) {
            float s = 0.f, ss = 0.f;
#pragma unroll
            for (int cc = 0; cc < 2; ++cc) {
                int ch = q * 2 + cc;
                float r8[8];
                rec8(J.r, swz(m, ch), r8);
                float* cp = &sC[row * 132 + ch * 8];
                float4 a0 = *(float4*)cp, a1 = *(float4*)(cp + 4);
                a0.x += r8[0]; a0.y += r8[1]; a0.z += r8[2]; a0.w += r8[3];
                a1.x += r8[4]; a1.y += r8[5]; a1.z += r8[6]; a1.w += r8[7];
                s  += a0.x + a0.y + a0.z + a0.w + a1.x + a1.y + a1.z + a1.w;
                ss += a0.x * a0.x + a0.y * a0.y + a0.z * a0.z + a0.w * a0.w +
                      a1.x * a1.x + a1.y * a1.y + a1.z * a1.z + a1.w * a1.w;
                *(float4*)cp = a0;
                *(float4*)(cp + 4) = a1;
            }
#pragma unroll
            for (int off = 1; off < 8; off <<= 1) {
                s  += __shfl_xor_sync(0xffffffffu, s,  off);
                ss += __shfl_xor_sync(0xffffffffu, ss, off);
            }
            mean = s * (1.0f / 128.0f);
            rstd = rsqrtf(ss * (1.0f / 128.0f) - mean * mean + LN_EPS);
        }
#pragma unroll
        for (int cc = 0; cc < 2; ++cc) {
            int ch = q * 2 + cc;
            int col = ch * 8;
            float* cp = &sC[row * 132 + col];
            float v[8];
            *(float4*)&v[0] = *(float4*)cp;
            *(float4*)&v[4] = *(float4*)(cp + 4);
            if (J.mode == M_LN) {
                float4 g0 = *(const float4*)&J.lng[col];
                float4 g1 = *(const float4*)&J.lng[col + 4];
                float4 o0 = *(const float4*)&J.lnb[col];
                float4 o1 = *(const float4*)&J.lnb[col + 4];
                v[0] = (v[0] - mean) * rstd * g0.x + o0.x;
                v[1] = (v[1] - mean) * rstd * g0.y + o0.y;
                v[2] = (v[2] - mean) * rstd * g0.z + o0.z;
                v[3] = (v[3] - mean) * rstd * g0.w + o0.w;
                v[4] = (v[4] - mean) * rstd * g1.x + o1.x;
                v[5] = (v[5] - mean) * rstd * g1.y + o1.y;
                v[6] = (v[6] - mean) * rstd * g1.z + o1.z;
                v[7] = (v[7] - mean) * rstd * g1.w + o1.w;
            }
            if (J.outf) {
                *(float4*)&J.outf[(size_t)m * J.ostride + J.ooff + col]     = *(float4*)&v[0];
                *(float4*)&J.outf[(size_t)m * J.ostride + J.ooff + col + 4] = *(float4*)&v[4];
            } else {
                *(uint4*)(J.o + swz(m, ch)) = pack8(v);
            }
        }
    }
}

// ---------------- prop body: 64 nodes/block, 2 nodes/warp, 16-lane rows ----
__device__ void prop_body(const PJob& P, int blk) {
    const int lane = threadIdx.x & 31, wid = threadIdx.x >> 5;
    const int half = lane >> 4, ch = lane & 15;
    for (int t = 0; t < 4; ++t) {
        const int i = blk * 64 + t * 16 + wid * 2 + half;
        const float di = g_dinv[i];
        float ac[8], a[8];
        prop_gather(P.n, i, ch, di, ac);
        rec8(P.r, swz(i, ch), a);                  // residual
        float v[8];
        float s = 0.f, ss = 0.f;
#pragma unroll
        for (int e = 0; e < 8; ++e) {
            v[e] = fmaxf(di * ac[e], 0.f) + a[e];
            s += v[e]; ss += v[e] * v[e];
        }
#pragma unroll
        for (int off = 1; off < 16; off <<= 1) {
            s  += __shfl_xor_sync(0xffffffffu, s,  off);
            ss += __shfl_xor_sync(0xffffffffu, ss, off);
        }
        float mean = s * (1.0f / 128.0f);
        float rstd = rsqrtf(ss * (1.0f / 128.0f) - mean * mean + LN_EPS);
        float4 g0 = *(const float4*)&P.lng[ch * 8];
        float4 g1 = *(const float4*)&P.lng[ch * 8 + 4];
        float4 o0 = *(const float4*)&P.lnb[ch * 8];
        float4 o1 = *(const float4*)&P.lnb[ch * 8 + 4];
        v[0] = (v[0] - mean) * rstd * g0.x + o0.x;
        v[1] = (v[1] - mean) * rstd * g0.y + o0.y;
        v[2] = (v[2] - mean) * rstd * g0.z + o0.z;
        v[3] = (v[3] - mean) * rstd * g0.w + o0.w;
        v[4] = (v[4] - mean) * rstd * g1.x + o1.x;
        v[5] = (v[5] - mean) * rstd * g1.y + o1.y;
        v[6] = (v[6] - mean) * rstd * g1.z + o1.z;
        v[7] = (v[7] - mean) * rstd * g1.w + o1.w;
        if (P.outf) {
            *(float4*)&P.outf[(size_t)i * P.ostride + P.ooff + ch * 8]     = *(float4*)&v[0];
            *(float4*)&P.outf[(size_t)i * P.ostride + P.ooff + ch * 8 + 4] = *(float4*)&v[4];
        } else {
            *(uint4*)(P.o + swz(i, ch)) = pack8(v);
        }
    }
}

#define GB (N_NODES / MTILE)    // 256 gemm tiles
#define PB (N_NODES / 64)       // 128 prop blocks

// ---------------- named step kernels ----------------------------------------
__global__ __launch_bounds__(THREADS, 4) void k_g2(GJob g0, GJob g1) {
    extern __shared__ __align__(256) char smem_raw[];
    int b = blockIdx.x;
    if (b < GB) gemm_body(g0, b, smem_raw);
    else        gemm_body(g1, b - GB, smem_raw);
}
__global__ __launch_bounds__(THREADS, 4) void k_gp(GJob g, PJob p) {
    extern __shared__ __align__(256) char smem_raw[];
    int b = blockIdx.x;
    if (b < GB) gemm_body(g, b, smem_raw);
    else        prop_body(p, b - GB);
}

// ---------------- driver ----------------------------------------------------
extern "C" void kernel_launch(void* const* d_in, const int* in_sizes, int n_in,
                              void* d_out, int out_size) {
    const float* x   = (const float*)d_in[0];
    const int*   nei = (const int*)  d_in[1];
    const int*   nbc = (const int*)  d_in[2];
    const float* gW  = (const float*)d_in[3];
    const float* gb  = (const float*)d_in[4];
    const float* glg = (const float*)d_in[5];
    const float* glb = (const float*)d_in[6];
    const float* pW  = (const float*)d_in[7];
    const float* pb  = (const float*)d_in[8];
    const float* mW  = (const float*)d_in[9];
    const float* mb  = (const float*)d_in[10];
    const float* slg = (const float*)d_in[11];
    const float* slb = (const float*)d_in[12];
    float* out = (float*)d_out;

    unsigned char *xp, *p0, *p1, *p2, *p3, *p4;
    cudaGetSymbolAddress((void**)&xp, g_x);
    cudaGetSymbolAddress((void**)&p0, g_p0);
    cudaGetSymbolAddress((void**)&p1, g_p1);
    cudaGetSymbolAddress((void**)&p2, g_p2);
    cudaGetSymbolAddress((void**)&p3, g_p3);
    cudaGetSymbolAddress((void**)&p4, g_p4);

    cudaFuncSetAttribute(k_g2, cudaFuncAttributeMaxDynamicSharedMemorySize, SMEM_TOTAL);
    cudaFuncSetAttribute(k_gp, cudaFuncAttributeMaxDynamicSharedMemorySize, SMEM_TOTAL);

    // --- GCN jobs (plane schedule avoids cross-block read/write aliasing) ---
    // step1: nxt0 = x@W0+b0 -> p0
    GJob G0  = { xp, nullptr, nullptr, gb, nullptr, nullptr, nullptr, p0,
                 nullptr, nullptr, nullptr, nullptr, nullptr, 0,
                 0, 1, M_PLAIN, D, 0 };
    // step2: stage h1 = LN(relu(prop(p0)) + p0) -> SMEM + p1; nxt1 = h1@W1 -> p4
    GJob G1p = { nullptr, nullptr, nullptr, gb + D, nullptr, nullptr, nullptr, p4,
                 p0, p0, glg, glb, p1, 1,
                 1, 1, M_PLAIN, D, 0 };
    // step3: stage h2 = LN(relu(prop(p4)) + p1) -> SMEM + p1; nxt2 = h2@W2 -> p0
    GJob G2p = { nullptr, nullptr, nullptr, gb + 2 * D, nullptr, nullptr, nullptr, p0,
                 p4, p1, glg + D, glb + D, p1, 1,
                 2, 1, M_PLAIN, D, 0 };
    // --- SAGE jobs (pool fused as chunk 1) ---
    GJob S0  = { xp, nullptr, nullptr, pb, nullptr, nullptr, nullptr, p2,
                 nullptr, nullptr, nullptr, nullptr, nullptr, 0,
                 3, 1, M_RELU, D, 0 };
    GJob S1  = { xp, p2, nullptr, mb, nullptr, nullptr, nullptr, p3,
                 nullptr, nullptr, nullptr, nullptr, nullptr, 0,
                 4, 2, M_RELU, D, 0 };
    GJob S2  = { p3, p3, p3, mb + D, slg, slb, nullptr, p2,
                 nullptr, nullptr, nullptr, nullptr, nullptr, 0,
                 6, 2, M_LN, D, 0 };
    GJob S3  = { p2, p2, p2, mb + 2 * D, slg + D, slb + D, out, nullptr,
                 nullptr, nullptr, nullptr, nullptr, nullptr, 0,
                 8, 2, M_LN, 2 * D, D };
    // step4: final GCN prop: out[:,0:128] = LN(relu(prop(p0)) + p1)
    PJob P2  = { p0, p1, glg + 2 * D, glb + 2 * D, out, nullptr, 2 * D, 0 };

    prep_all_kernel<<<106, 256>>>(nei, nbc, gW, pW, mW, x);
    prep2_kernel<<<N_NODES / 256, 256>>>();

    k_g2<<<2 * GB, THREADS, SMEM_TOTAL>>>(G0, S0);        // step1: G0  | S0
    k_g2<<<2 * GB, THREADS, SMEM_TOTAL>>>(G1p, S1);       // step2: G1p | S1
    k_g2<<<2 * GB, THREADS, SMEM_TOTAL>>>(G2p, S2);       // step3: G2p | S2
    k_gp<<<GB + PB, THREADS, SMEM_TOTAL>>>(S3, P2);       // step4: S3  | P2
}